// round 9
// baseline (speedup 1.0000x reference)
#include <cuda_runtime.h>
#include <cuda_bf16.h>
#include <math.h>

#define BN 8192
#define NN 100000
#define DD 8
#define KK 32
#define CC 100
#define TOTAL (BN + NN)
#define NTILES ((TOTAL + 127) / 128)   // 846
#define GRID_MLP 296                   // 2 blocks/SM persistent

#define NSTR 132          // stride mod 32 == 4 -> B-frag LDS conflict-free
#define KT   7            // k-tiles of 16 covering K=100 (pad 112)
#define MT2  7            // m-tiles of 16 covering M=100 (pad 112)
#define MT3  2            // m-tiles of 16 covering M=30  (pad 32)
#define NW2  (KT * MT2 * 128)   // 6272 u32
#define NW3  (KT * MT3 * 128)   // 1792 u32

// ---- smem layout (bytes) ----
#define SM_HS    0                       // Hs fp32 [112][NSTR] = 59136
#define SM_W2FH  59136                   // W2 hi frags: 6272 u32 = 25088
#define SM_W2FL  84224                   // W2 lo frags: 25088
#define SM_MISC  109312                  // mf floats [494]
#define SMEM_TOTAL 111360

// Feature scratch: [0..BN) queries, [BN..TOTAL) nodes, (x,y) pairs.
__device__ float g_feat[TOTAL * 2];

// W3 fragments: written redundantly (identical values) by every block in phase 0;
// each block reads only after its own writes + __syncthreads, so no cross-block
// ordering is required.
__device__ unsigned g_W3hi[NW3], g_W3lo[NW3];

__device__ __forceinline__ unsigned bf2(float lo, float hi) {  // pack {lo, hi} bf16x2
    unsigned r;
    asm("cvt.rn.bf16x2.f32 %0, %1, %2;" : "=r"(r) : "f"(hi), "f"(lo));
    return r;
}
__device__ __forceinline__ float blo(unsigned p) { return __uint_as_float(p << 16); }
__device__ __forceinline__ float bhi(unsigned p) { return __uint_as_float(p & 0xffff0000u); }

__device__ __forceinline__ void mma16(float (&c)[4], const uint4& a, unsigned b0, unsigned b1) {
    asm("mma.sync.aligned.m16n8k16.row.col.f32.bf16.bf16.f32 "
        "{%0,%1,%2,%3}, {%4,%5,%6,%7}, {%8,%9}, {%0,%1,%2,%3};"
        : "+f"(c[0]), "+f"(c[1]), "+f"(c[2]), "+f"(c[3])
        : "r"(a.x), "r"(a.y), "r"(a.z), "r"(a.w), "r"(b0), "r"(b1));
}

// ---------------- persistent MLP kernel: 256 threads, 128 points per tile ----------------
__global__ __launch_bounds__(256, 2)
void mlp_kernel(const float* __restrict__ x, const float* __restrict__ nd,
                const float* __restrict__ W1, const float* __restrict__ b1,
                const float* __restrict__ W2, const float* __restrict__ b2,
                const float* __restrict__ W3, const float* __restrict__ b3,
                const float* __restrict__ W4, const float* __restrict__ b4)
{
    extern __shared__ char smraw[];
    float* Hs = (float*)(smraw + SM_HS);
    uint4* W2FH = (uint4*)(smraw + SM_W2FH);
    uint4* W2FL = (uint4*)(smraw + SM_W2FL);
    float* mf = (float*)(smraw + SM_MISC);

    const int tid = threadIdx.x;
    const int lane = tid & 31, warp = tid >> 5;
    const int g = lane >> 2, t = lane & 3;
    const int n0 = warp * 16;              // each warp owns 16 points (2 n-tiles of 8)

    // ---- phase 0: pack W2/W3 into bf16 hi/lo m16n8k16 A-fragments + small params ----
    {
        unsigned* w2h = (unsigned*)(smraw + SM_W2FH);
        unsigned* w2l = (unsigned*)(smraw + SM_W2FL);
        for (int idx = tid; idx < NW2 + NW3; idx += 256) {
            const bool is3 = idx >= NW2;
            const int id = is3 ? idx - NW2 : idx;
            const int r = id & 3, ln = (id >> 2) & 31, q = id >> 7;
            const int nmt = is3 ? MT3 : MT2;
            const int mt = q % nmt, kt = q / nmt;
            const int row = mt * 16 + (ln >> 2) + (r & 1) * 8;
            const int col = kt * 16 + 2 * (ln & 3) + (r >> 1) * 8;
            const int rmax = is3 ? 30 : 100;
            const float* W = is3 ? W3 : W2;
            float w0 = 0.f, w1 = 0.f;
            if (row < rmax) {
                if (col < 100)     w0 = W[row * 100 + col];
                if (col + 1 < 100) w1 = W[row * 100 + col + 1];
            }
            const float h0 = __bfloat162float(__float2bfloat16_rn(w0));
            const float h1 = __bfloat162float(__float2bfloat16_rn(w1));
            const unsigned hp = bf2(h0, h1);
            const unsigned lp = bf2(w0 - h0, w1 - h1);
            if (is3) { g_W3hi[id] = hp; g_W3lo[id] = lp; }   // redundant identical write
            else     { w2h[id] = hp;    w2l[id] = lp; }
        }
        for (int i = tid; i < 200; i += 256) mf[i] = W1[i];
        if (tid < 100) { mf[200 + tid] = b1[tid]; mf[300 + tid] = b2[tid]; }
        if (tid < 32)  mf[400 + tid] = (tid < 30) ? b3[tid] : 0.f;
        if (tid < 60)  mf[432 + tid] = W4[tid];
        if (tid < 2)   mf[492 + tid] = b4[tid];
    }
    __syncthreads();

    const uint4* W3h4 = (const uint4*)g_W3hi;
    const uint4* W3l4 = (const uint4*)g_W3lo;

    for (int tile = blockIdx.x; tile < NTILES; tile += GRID_MLP) {
        const int pbase = tile * 128;

        // ---- layer 1: 2 -> 100, ReLU. Two threads per point (j-halves). ----
        {
            const int p = tid & 127, half = tid >> 7;
            const int pg = pbase + p;
            float px = 0.f, py = 0.f;
            if (pg < TOTAL) {
                const float2 v = (pg < BN) ? ((const float2*)x)[pg]
                                           : ((const float2*)nd)[pg - BN];
                px = v.x; py = v.y;
            }
            const int j0 = half * 50;
            #pragma unroll 10
            for (int j = j0; j < j0 + 50; j++) {
                float v = fmaf(mf[2 * j], px, fmaf(mf[2 * j + 1], py, mf[200 + j]));
                Hs[j * NSTR + p] = fmaxf(v, 0.f);
            }
            for (int i = tid; i < 12 * NSTR; i += 256) Hs[100 * NSTR + i] = 0.f;
        }
        __syncthreads();

        // ---- layer 2: 100 -> 100 via bf16 split-2 mma (3 products), A-frags from SMEM ----
        float C[MT2][2][4];
        #pragma unroll
        for (int mt = 0; mt < MT2; mt++)
            #pragma unroll
            for (int nt = 0; nt < 2; nt++)
                #pragma unroll
                for (int r = 0; r < 4; r++) C[mt][nt][r] = 0.f;

        for (int kt = 0; kt < KT; kt++) {
            const int k0 = kt * 16 + 2 * t;
            unsigned bh[2][2], bl[2][2];
            #pragma unroll
            for (int nt = 0; nt < 2; nt++) {
                const int c = n0 + nt * 8 + g;
                const float r0 = Hs[(k0 + 0) * NSTR + c];
                const float r1 = Hs[(k0 + 1) * NSTR + c];
                const float r2 = Hs[(k0 + 8) * NSTR + c];
                const float r3 = Hs[(k0 + 9) * NSTR + c];
                bh[nt][0] = bf2(r0, r1);
                bh[nt][1] = bf2(r2, r3);
                bl[nt][0] = bf2(r0 - blo(bh[nt][0]), r1 - bhi(bh[nt][0]));
                bl[nt][1] = bf2(r2 - blo(bh[nt][1]), r3 - bhi(bh[nt][1]));
            }
            #pragma unroll
            for (int mt = 0; mt < MT2; mt++) {
                const int base = (kt * MT2 + mt) * 32 + lane;
                const uint4 ah = W2FH[base];
                const uint4 al = W2FL[base];
                #pragma unroll
                for (int nt = 0; nt < 2; nt++) {
                    mma16(C[mt][nt], ah, bh[nt][0], bh[nt][1]);
                    mma16(C[mt][nt], ah, bl[nt][0], bl[nt][1]);
                    mma16(C[mt][nt], al, bh[nt][0], bh[nt][1]);
                }
            }
        }
        __syncthreads();   // all layer-2 reads of Hs complete

        // write h2 = relu(C + b2) into Hs rows 0..111 (rows >=100 zeroed)
        #pragma unroll
        for (int mt = 0; mt < MT2; mt++)
            #pragma unroll
            for (int half = 0; half < 2; half++) {
                const int row = mt * 16 + g + half * 8;
                const float bias = (row < 100) ? mf[300 + row] : 0.f;
                #pragma unroll
                for (int nt = 0; nt < 2; nt++) {
                    float v0 = C[mt][nt][2 * half + 0] + bias;
                    float v1 = C[mt][nt][2 * half + 1] + bias;
                    if (row >= 100) { v0 = 0.f; v1 = 0.f; }
                    else { v0 = fmaxf(v0, 0.f); v1 = fmaxf(v1, 0.f); }
                    Hs[row * NSTR + n0 + nt * 8 + 2 * t] = v0;
                    Hs[row * NSTR + n0 + nt * 8 + 2 * t + 1] = v1;
                }
            }
        __syncthreads();

        // ---- layer 3: 100 -> 30 via bf16 split-2 mma (W3 frags from L2) ----
        float D[MT3][2][4];
        #pragma unroll
        for (int mt = 0; mt < MT3; mt++)
            #pragma unroll
            for (int nt = 0; nt < 2; nt++)
                #pragma unroll
                for (int r = 0; r < 4; r++) D[mt][nt][r] = 0.f;

        for (int kt = 0; kt < KT; kt++) {
            uint4 ah[MT3], al[MT3];
            #pragma unroll
            for (int mt = 0; mt < MT3; mt++) {
                const int base = (kt * MT3 + mt) * 32 + lane;
                ah[mt] = W3h4[base];
                al[mt] = W3l4[base];
            }
            const int k0 = kt * 16 + 2 * t;
            unsigned bh[2][2], bl[2][2];
            #pragma unroll
            for (int nt = 0; nt < 2; nt++) {
                const int c = n0 + nt * 8 + g;
                const float r0 = Hs[(k0 + 0) * NSTR + c];
                const float r1 = Hs[(k0 + 1) * NSTR + c];
                const float r2 = Hs[(k0 + 8) * NSTR + c];
                const float r3 = Hs[(k0 + 9) * NSTR + c];
                bh[nt][0] = bf2(r0, r1);
                bh[nt][1] = bf2(r2, r3);
                bl[nt][0] = bf2(r0 - blo(bh[nt][0]), r1 - bhi(bh[nt][0]));
                bl[nt][1] = bf2(r2 - blo(bh[nt][1]), r3 - bhi(bh[nt][1]));
            }
            #pragma unroll
            for (int mt = 0; mt < MT3; mt++)
                #pragma unroll
                for (int nt = 0; nt < 2; nt++) {
                    mma16(D[mt][nt], ah[mt], bh[nt][0], bh[nt][1]);
                    mma16(D[mt][nt], ah[mt], bl[nt][0], bl[nt][1]);
                    mma16(D[mt][nt], al[mt], bh[nt][0], bh[nt][1]);
                }
        }

        // ---- layer 4: 30 -> 2 directly from D fragments, warp shuffle reduce ----
        {
            float acc[2][2][2];   // [nt][col01][out01]
            #pragma unroll
            for (int nt = 0; nt < 2; nt++)
                #pragma unroll
                for (int c2 = 0; c2 < 2; c2++) { acc[nt][c2][0] = 0.f; acc[nt][c2][1] = 0.f; }
            #pragma unroll
            for (int mt = 0; mt < MT3; mt++)
                #pragma unroll
                for (int half = 0; half < 2; half++) {
                    const int row = mt * 16 + g + half * 8;
                    const float w0 = (row < 30) ? mf[432 + row] : 0.f;   // W4[0][row]
                    const float w1 = (row < 30) ? mf[462 + row] : 0.f;   // W4[1][row]
                    const float bias = (row < 30) ? mf[400 + row] : 0.f;
                    #pragma unroll
                    for (int nt = 0; nt < 2; nt++) {
                        const float h0 = fmaxf(D[mt][nt][2 * half + 0] + bias, 0.f);
                        const float h1 = fmaxf(D[mt][nt][2 * half + 1] + bias, 0.f);
                        acc[nt][0][0] = fmaf(w0, h0, acc[nt][0][0]);
                        acc[nt][0][1] = fmaf(w1, h0, acc[nt][0][1]);
                        acc[nt][1][0] = fmaf(w0, h1, acc[nt][1][0]);
                        acc[nt][1][1] = fmaf(w1, h1, acc[nt][1][1]);
                    }
                }
            #pragma unroll
            for (int o = 4; o <= 16; o <<= 1)
                #pragma unroll
                for (int nt = 0; nt < 2; nt++)
                    #pragma unroll
                    for (int c2 = 0; c2 < 2; c2++) {
                        acc[nt][c2][0] += __shfl_xor_sync(0xffffffffu, acc[nt][c2][0], o);
                        acc[nt][c2][1] += __shfl_xor_sync(0xffffffffu, acc[nt][c2][1], o);
                    }
            if (g == 0) {   // lanes 0..3 hold final sums for their 4 point-columns
                #pragma unroll
                for (int nt = 0; nt < 2; nt++)
                    #pragma unroll
                    for (int c2 = 0; c2 < 2; c2++) {
                        const int pg = pbase + n0 + nt * 8 + 2 * t + c2;
                        if (pg < TOTAL)
                            ((float2*)g_feat)[pg] = make_float2(acc[nt][c2][0] + mf[492],
                                                                acc[nt][c2][1] + mf[493]);
                    }
            }
        }
        __syncthreads();   // Hs reads (layer 3) done before next tile's layer-1 writes
    }
}

// ---------------- routing kernel: one block per query b ----------------
__global__ __launch_bounds__(256)
void route_kernel(const int* __restrict__ nbr_idx, const int* __restrict__ labels,
                  float* __restrict__ out)
{
    __shared__ float p_s[CC];
    __shared__ float terms[DD - 1];

    const int b = blockIdx.x;
    const int tid = threadIdx.x;
    const int d = tid >> 5, lane = tid & 31;

    if (tid < CC) p_s[tid] = 0.f;
    __syncthreads();

    const float2 q = ((const float2*)g_feat)[b];
    const int idx = nbr_idx[b * (DD * KK) + tid];
    const float2 g = ((const float2*)g_feat)[BN + idx];

    const float dx = g.x - q.x + 1e-6f;
    const float dy = g.y - q.y + 1e-6f;
    const float dist = sqrtf(fmaf(dx, dx, dy * dy));

    // dist >= 0 -> IEEE bit pattern is order-preserving: one u32 redux does the max(neg).
    const float mind = __uint_as_float(__reduce_min_sync(0xffffffffu, __float_as_uint(dist)));
    const float e = __expf(mind - dist);   // argmax lane is exactly exp(0) = 1
    float s = e;
    #pragma unroll
    for (int o = 16; o > 0; o >>= 1) s += __shfl_xor_sync(0xffffffffu, s, o);

    if (d < DD - 1) {
        if (lane == 0) terms[d] = __logf(__fdividef(1.0f, s) + 1e-4f);
    } else {
        const int c = labels[idx];
        atomicAdd(&p_s[c], __fdividef(e, s));
    }
    __syncthreads();

    if (tid < CC) {
        float tsum = terms[0] + terms[1] + terms[2] + terms[3] + terms[4] + terms[5] + terms[6];
        out[(long)b * CC + tid] = __logf(p_s[tid] + 1e-4f) + tsum;
    }
}

extern "C" void kernel_launch(void* const* d_in, const int* in_sizes, int n_in,
                              void* d_out, int out_size)
{
    const float* x      = (const float*)d_in[0];
    const float* nd     = (const float*)d_in[1];
    const float* W1     = (const float*)d_in[2];
    const float* b1     = (const float*)d_in[3];
    const float* W2     = (const float*)d_in[4];
    const float* b2     = (const float*)d_in[5];
    const float* W3     = (const float*)d_in[6];
    const float* b3     = (const float*)d_in[7];
    const float* W4     = (const float*)d_in[8];
    const float* b4     = (const float*)d_in[9];
    const int*   labels = (const int*)d_in[10];
    const int*   nbr    = (const int*)d_in[11];
    float* out = (float*)d_out;

    cudaFuncSetAttribute(mlp_kernel, cudaFuncAttributeMaxDynamicSharedMemorySize, SMEM_TOTAL);

    mlp_kernel<<<GRID_MLP, 256, SMEM_TOTAL>>>(x, nd, W1, b1, W2, b2, W3, b3, W4, b4);
    route_kernel<<<BN, 256>>>(nbr, labels, out);
}

// round 10
// speedup vs baseline: 1.2999x; 1.2999x over previous
#include <cuda_runtime.h>
#include <cuda_fp16.h>
#include <math.h>

#define BN 8192
#define NN 100000
#define DD 8
#define KK 32
#define CC 100
#define TOTAL (BN + NN)
#define NTILES ((TOTAL + 127) / 128)   // 846
#define GRID_MLP 296                   // 2 blocks/SM persistent

#define NSTR 132          // stride mod 32 == 4 -> B-frag LDS conflict-free
#define KT   7            // k-tiles of 16 covering K=100 (pad 112)
#define MT2  7            // m-tiles of 16 covering M=100 (pad 112)
#define MT3  2            // m-tiles of 16 covering M=30  (pad 32)
#define NW2  (KT * MT2 * 128)   // 6272 u32
#define NW3  (KT * MT3 * 128)   // 1792 u32

// ---- smem layout (bytes) ----
#define SM_HS    0                       // Hs fp32 [112][NSTR] = 59136
#define SM_W2FH  59136                   // W2 hi frags: 6272 u32 = 25088
#define SM_W2FL  84224                   // W2 lo frags: 25088
#define SM_MISC  109312                  // mf floats [494]
#define SMEM_TOTAL 111360

// Feature scratch: [0..BN) queries, [BN..TOTAL) nodes, (x,y) pairs.
__device__ float g_feat[TOTAL * 2];

// Weights split 2-level into fp16 (hi + residual lo), packed in m16n8k16 A-fragment order.
__device__ unsigned g_W2hi[NW2], g_W2lo[NW2];
__device__ unsigned g_W3hi[NW3], g_W3lo[NW3];

__device__ __forceinline__ unsigned h2pk(float lo, float hi) {  // pack {lo, hi} as f16x2
    unsigned r;
    asm("cvt.rn.f16x2.f32 %0, %1, %2;" : "=r"(r) : "f"(hi), "f"(lo));
    return r;
}

__device__ __forceinline__ void mma16(float (&c)[4], const uint4& a, unsigned b0, unsigned b1) {
    asm("mma.sync.aligned.m16n8k16.row.col.f32.f16.f16.f32 "
        "{%0,%1,%2,%3}, {%4,%5,%6,%7}, {%8,%9}, {%0,%1,%2,%3};"
        : "+f"(c[0]), "+f"(c[1]), "+f"(c[2]), "+f"(c[3])
        : "r"(a.x), "r"(a.y), "r"(a.z), "r"(a.w), "r"(b0), "r"(b1));
}

// ---------------- pack kernel: split W2/W3 into fp16 hi/lo fragment arrays ----------------
__global__ void pack_kernel(const float* __restrict__ W2, const float* __restrict__ W3)
{
    const int stride = gridDim.x * blockDim.x;
    for (int idx = blockIdx.x * blockDim.x + threadIdx.x; idx < NW2 + NW3; idx += stride) {
        const bool is3 = idx >= NW2;
        const int id = is3 ? idx - NW2 : idx;
        const int r = id & 3, lane = (id >> 2) & 31, q = id >> 7;
        const int nmt = is3 ? MT3 : MT2;
        const int mt = q % nmt, kt = q / nmt;
        const int row = mt * 16 + (lane >> 2) + (r & 1) * 8;
        const int col = kt * 16 + 2 * (lane & 3) + (r >> 1) * 8;
        const int rmax = is3 ? 30 : 100;
        const float* W = is3 ? W3 : W2;
        float w0 = 0.f, w1 = 0.f;
        if (row < rmax) {
            if (col < 100)     w0 = W[row * 100 + col];
            if (col + 1 < 100) w1 = W[row * 100 + col + 1];
        }
        const float h0 = __half2float(__float2half_rn(w0));
        const float h1 = __half2float(__float2half_rn(w1));
        const unsigned hp = h2pk(h0, h1);
        const unsigned lp = h2pk(w0 - h0, w1 - h1);
        if (is3) { g_W3hi[id] = hp; g_W3lo[id] = lp; }
        else     { g_W2hi[id] = hp; g_W2lo[id] = lp; }
    }
}

// ---------------- persistent MLP kernel: 256 threads, 128 points per tile ----------------
__global__ __launch_bounds__(256, 2)
void mlp_kernel(const float* __restrict__ x, const float* __restrict__ nd,
                const float* __restrict__ W1, const float* __restrict__ b1,
                const float* __restrict__ b2, const float* __restrict__ b3,
                const float* __restrict__ W4, const float* __restrict__ b4)
{
    extern __shared__ char smraw[];
    float* Hs = (float*)(smraw + SM_HS);
    const uint4* W2FH = (const uint4*)(smraw + SM_W2FH);
    const uint4* W2FL = (const uint4*)(smraw + SM_W2FL);
    float* mf = (float*)(smraw + SM_MISC);

    const int tid = threadIdx.x;
    const int lane = tid & 31, warp = tid >> 5;
    const int g = lane >> 2, t = lane & 3;
    const int n0 = warp * 16;              // each warp owns 16 points (2 n-tiles of 8)

    // ---- phase 0: coalesced copy of packed W2 fragments + small params ----
    {
        uint4* dstH = (uint4*)(smraw + SM_W2FH);
        uint4* dstL = (uint4*)(smraw + SM_W2FL);
        const uint4* srcH = (const uint4*)g_W2hi;
        const uint4* srcL = (const uint4*)g_W2lo;
        for (int i = tid; i < NW2 / 4; i += 256) { dstH[i] = srcH[i]; dstL[i] = srcL[i]; }
        for (int i = tid; i < 200; i += 256) mf[i] = W1[i];
        if (tid < 100) { mf[200 + tid] = b1[tid]; mf[300 + tid] = b2[tid]; }
        if (tid < 32)  mf[400 + tid] = (tid < 30) ? b3[tid] : 0.f;
        if (tid < 60)  mf[432 + tid] = W4[tid];
        if (tid < 2)   mf[492 + tid] = b4[tid];
    }
    __syncthreads();

    const uint4* W3h4 = (const uint4*)g_W3hi;
    const uint4* W3l4 = (const uint4*)g_W3lo;

    for (int tile = blockIdx.x; tile < NTILES; tile += GRID_MLP) {
        const int pbase = tile * 128;

        // ---- layer 1: 2 -> 100, ReLU. Two threads per point (j-halves). ----
        {
            const int p = tid & 127, half = tid >> 7;
            const int pg = pbase + p;
            float px = 0.f, py = 0.f;
            if (pg < TOTAL) {
                const float2 v = (pg < BN) ? ((const float2*)x)[pg]
                                           : ((const float2*)nd)[pg - BN];
                px = v.x; py = v.y;
            }
            const int j0 = half * 50;
            #pragma unroll 10
            for (int j = j0; j < j0 + 50; j++) {
                float v = fmaf(mf[2 * j], px, fmaf(mf[2 * j + 1], py, mf[200 + j]));
                Hs[j * NSTR + p] = fmaxf(v, 0.f);
            }
            for (int i = tid; i < 12 * NSTR; i += 256) Hs[100 * NSTR + i] = 0.f;
        }
        __syncthreads();

        // ---- layer 2: 100 -> 100 via fp16 2-product mma (acts single fp16) ----
        float C[MT2][2][4];
        #pragma unroll
        for (int mt = 0; mt < MT2; mt++)
            #pragma unroll
            for (int nt = 0; nt < 2; nt++)
                #pragma unroll
                for (int r = 0; r < 4; r++) C[mt][nt][r] = 0.f;

        for (int kt = 0; kt < KT; kt++) {
            const int k0 = kt * 16 + 2 * t;
            unsigned bf[2][2];
            #pragma unroll
            for (int nt = 0; nt < 2; nt++) {
                const int c = n0 + nt * 8 + g;
                bf[nt][0] = h2pk(Hs[(k0 + 0) * NSTR + c], Hs[(k0 + 1) * NSTR + c]);
                bf[nt][1] = h2pk(Hs[(k0 + 8) * NSTR + c], Hs[(k0 + 9) * NSTR + c]);
            }
            #pragma unroll
            for (int mt = 0; mt < MT2; mt++) {
                const int base = (kt * MT2 + mt) * 32 + lane;
                const uint4 ah = W2FH[base];
                const uint4 al = W2FL[base];
                #pragma unroll
                for (int nt = 0; nt < 2; nt++) {
                    mma16(C[mt][nt], ah, bf[nt][0], bf[nt][1]);
                    mma16(C[mt][nt], al, bf[nt][0], bf[nt][1]);
                }
            }
        }
        __syncthreads();   // all layer-2 reads of Hs complete

        // write h2 = relu(C + b2) into Hs rows 0..111 (rows >=100 zeroed)
        #pragma unroll
        for (int mt = 0; mt < MT2; mt++)
            #pragma unroll
            for (int half = 0; half < 2; half++) {
                const int row = mt * 16 + g + half * 8;
                const float bias = (row < 100) ? mf[300 + row] : 0.f;
                #pragma unroll
                for (int nt = 0; nt < 2; nt++) {
                    float v0 = C[mt][nt][2 * half + 0] + bias;
                    float v1 = C[mt][nt][2 * half + 1] + bias;
                    if (row >= 100) { v0 = 0.f; v1 = 0.f; }
                    else { v0 = fmaxf(v0, 0.f); v1 = fmaxf(v1, 0.f); }
                    Hs[row * NSTR + n0 + nt * 8 + 2 * t] = v0;
                    Hs[row * NSTR + n0 + nt * 8 + 2 * t + 1] = v1;
                }
            }
        __syncthreads();

        // ---- layer 3: 100 -> 30 via fp16 2-product mma (W3 frags from L2) ----
        float D[MT3][2][4];
        #pragma unroll
        for (int mt = 0; mt < MT3; mt++)
            #pragma unroll
            for (int nt = 0; nt < 2; nt++)
                #pragma unroll
                for (int r = 0; r < 4; r++) D[mt][nt][r] = 0.f;

        for (int kt = 0; kt < KT; kt++) {
            uint4 ah[MT3], al[MT3];
            #pragma unroll
            for (int mt = 0; mt < MT3; mt++) {
                const int base = (kt * MT3 + mt) * 32 + lane;
                ah[mt] = W3h4[base];
                al[mt] = W3l4[base];
            }
            const int k0 = kt * 16 + 2 * t;
            unsigned bf[2][2];
            #pragma unroll
            for (int nt = 0; nt < 2; nt++) {
                const int c = n0 + nt * 8 + g;
                bf[nt][0] = h2pk(Hs[(k0 + 0) * NSTR + c], Hs[(k0 + 1) * NSTR + c]);
                bf[nt][1] = h2pk(Hs[(k0 + 8) * NSTR + c], Hs[(k0 + 9) * NSTR + c]);
            }
            #pragma unroll
            for (int mt = 0; mt < MT3; mt++)
                #pragma unroll
                for (int nt = 0; nt < 2; nt++) {
                    mma16(D[mt][nt], ah[mt], bf[nt][0], bf[nt][1]);
                    mma16(D[mt][nt], al[mt], bf[nt][0], bf[nt][1]);
                }
        }

        // ---- layer 4: 30 -> 2 directly from D fragments, warp shuffle reduce ----
        {
            float acc[2][2][2];   // [nt][col01][out01]
            #pragma unroll
            for (int nt = 0; nt < 2; nt++)
                #pragma unroll
                for (int c2 = 0; c2 < 2; c2++) { acc[nt][c2][0] = 0.f; acc[nt][c2][1] = 0.f; }
            #pragma unroll
            for (int mt = 0; mt < MT3; mt++)
                #pragma unroll
                for (int half = 0; half < 2; half++) {
                    const int row = mt * 16 + g + half * 8;
                    const float w0 = (row < 30) ? mf[432 + row] : 0.f;   // W4[0][row]
                    const float w1 = (row < 30) ? mf[462 + row] : 0.f;   // W4[1][row]
                    const float bias = (row < 30) ? mf[400 + row] : 0.f;
                    #pragma unroll
                    for (int nt = 0; nt < 2; nt++) {
                        const float h0 = fmaxf(D[mt][nt][2 * half + 0] + bias, 0.f);
                        const float h1 = fmaxf(D[mt][nt][2 * half + 1] + bias, 0.f);
                        acc[nt][0][0] = fmaf(w0, h0, acc[nt][0][0]);
                        acc[nt][0][1] = fmaf(w1, h0, acc[nt][0][1]);
                        acc[nt][1][0] = fmaf(w0, h1, acc[nt][1][0]);
                        acc[nt][1][1] = fmaf(w1, h1, acc[nt][1][1]);
                    }
                }
            #pragma unroll
            for (int o = 4; o <= 16; o <<= 1)
                #pragma unroll
                for (int nt = 0; nt < 2; nt++)
                    #pragma unroll
                    for (int c2 = 0; c2 < 2; c2++) {
                        acc[nt][c2][0] += __shfl_xor_sync(0xffffffffu, acc[nt][c2][0], o);
                        acc[nt][c2][1] += __shfl_xor_sync(0xffffffffu, acc[nt][c2][1], o);
                    }
            if (g == 0) {   // lanes 0..3 hold final sums for their 4 point-columns
                #pragma unroll
                for (int nt = 0; nt < 2; nt++)
                    #pragma unroll
                    for (int c2 = 0; c2 < 2; c2++) {
                        const int pg = pbase + n0 + nt * 8 + 2 * t + c2;
                        if (pg < TOTAL)
                            ((float2*)g_feat)[pg] = make_float2(acc[nt][c2][0] + mf[492],
                                                                acc[nt][c2][1] + mf[493]);
                    }
            }
        }
        __syncthreads();   // Hs reads (layer 3) done before next tile's layer-1 writes
    }
}

// ---------------- routing kernel: one block per query b ----------------
__global__ __launch_bounds__(256)
void route_kernel(const int* __restrict__ nbr_idx, const int* __restrict__ labels,
                  float* __restrict__ out)
{
    __shared__ float p_s[CC];
    __shared__ float terms[DD - 1];

    const int b = blockIdx.x;
    const int tid = threadIdx.x;
    const int d = tid >> 5, lane = tid & 31;

    if (tid < CC) p_s[tid] = 0.f;
    __syncthreads();

    const float2 q = ((const float2*)g_feat)[b];
    const int idx = nbr_idx[b * (DD * KK) + tid];
    const float2 g = ((const float2*)g_feat)[BN + idx];

    const float dx = g.x - q.x + 1e-6f;
    const float dy = g.y - q.y + 1e-6f;
    const float dist = sqrtf(fmaf(dx, dx, dy * dy));

    // dist >= 0 -> IEEE bits are order-preserving: one u32 redux.min == max(-dist).
    const float mind = __uint_as_float(__reduce_min_sync(0xffffffffu, __float_as_uint(dist)));
    const float e = __expf(mind - dist);   // argmax lane is exactly exp(0) = 1
    float s = e;
    #pragma unroll
    for (int o = 16; o > 0; o >>= 1) s += __shfl_xor_sync(0xffffffffu, s, o);

    if (d < DD - 1) {
        if (lane == 0) terms[d] = __logf(__fdividef(1.0f, s) + 1e-4f);
    } else {
        const int c = labels[idx];
        atomicAdd(&p_s[c], __fdividef(e, s));
    }
    __syncthreads();

    if (tid < CC) {
        float tsum = terms[0] + terms[1] + terms[2] + terms[3] + terms[4] + terms[5] + terms[6];
        out[(long)b * CC + tid] = __logf(p_s[tid] + 1e-4f) + tsum;
    }
}

extern "C" void kernel_launch(void* const* d_in, const int* in_sizes, int n_in,
                              void* d_out, int out_size)
{
    const float* x      = (const float*)d_in[0];
    const float* nd     = (const float*)d_in[1];
    const float* W1     = (const float*)d_in[2];
    const float* b1     = (const float*)d_in[3];
    const float* W2     = (const float*)d_in[4];
    const float* b2     = (const float*)d_in[5];
    const float* W3     = (const float*)d_in[6];
    const float* b3     = (const float*)d_in[7];
    const float* W4     = (const float*)d_in[8];
    const float* b4     = (const float*)d_in[9];
    const int*   labels = (const int*)d_in[10];
    const int*   nbr    = (const int*)d_in[11];
    float* out = (float*)d_out;

    cudaFuncSetAttribute(mlp_kernel, cudaFuncAttributeMaxDynamicSharedMemorySize, SMEM_TOTAL);

    pack_kernel<<<64, 256>>>(W2, W3);
    mlp_kernel<<<GRID_MLP, 256, SMEM_TOTAL>>>(x, nd, W1, b1, b2, b3, W4, b4);
    route_kernel<<<BN, 256>>>(nbr, labels, out);
}

// round 12
// speedup vs baseline: 1.5529x; 1.1946x over previous
#include <cuda_runtime.h>
#include <cuda_fp16.h>
#include <math.h>

#define BN 8192
#define NN 100000
#define DD 8
#define KK 32
#define CC 100
#define TOTAL (BN + NN)
#define NTILES ((TOTAL + 127) / 128)   // 846
#define GRID_MLP 296                   // 2 blocks/SM persistent

#define NSTR 132          // stride mod 32 == 4 -> B-frag LDS conflict-free
#define KT   7            // k-tiles of 16 covering K=100 (pad 112)
#define MT2  7            // m-tiles of 16 covering M=100 (pad 112)
#define MT3  2            // m-tiles of 16 covering M=30  (pad 32)
#define NW2  (KT * MT2 * 128)   // 6272 u32 (each = 2 fp16)
#define NW3  (KT * MT3 * 128)   // 1792 u32

// ---- smem layout (bytes) ----
#define SM_HS    0                       // Hs fp32 [112][NSTR] = 59136
#define SM_W2F   59136                   // W2 frags: 6272 u32 = 25088
#define SM_MISC  84224                   // mf floats [494]
#define SMEM_TOTAL 86272

// Feature scratch: [0..BN) queries, [BN..TOTAL) nodes, (x,y) pairs.
__device__ float g_feat[TOTAL * 2];

// Weights as plain fp16, packed in m16n8k16 A-fragment order.
__device__ unsigned g_W2f[NW2];
__device__ unsigned g_W3f[NW3];

__device__ __forceinline__ unsigned h2pk(float lo, float hi) {  // pack {lo, hi} as f16x2
    unsigned r;
    asm("cvt.rn.f16x2.f32 %0, %1, %2;" : "=r"(r) : "f"(hi), "f"(lo));
    return r;
}

__device__ __forceinline__ void mma16(float (&c)[4], const uint4& a, unsigned b0, unsigned b1) {
    asm("mma.sync.aligned.m16n8k16.row.col.f32.f16.f16.f32 "
        "{%0,%1,%2,%3}, {%4,%5,%6,%7}, {%8,%9}, {%0,%1,%2,%3};"
        : "+f"(c[0]), "+f"(c[1]), "+f"(c[2]), "+f"(c[3])
        : "r"(a.x), "r"(a.y), "r"(a.z), "r"(a.w), "r"(b0), "r"(b1));
}

// ---------------- pack kernel: W2/W3 -> fp16 fragment arrays ----------------
__global__ void pack_kernel(const float* __restrict__ W2, const float* __restrict__ W3)
{
    const int stride = gridDim.x * blockDim.x;
    for (int idx = blockIdx.x * blockDim.x + threadIdx.x; idx < NW2 + NW3; idx += stride) {
        const bool is3 = idx >= NW2;
        const int id = is3 ? idx - NW2 : idx;
        const int r = id & 3, lane = (id >> 2) & 31, q = id >> 7;
        const int nmt = is3 ? MT3 : MT2;
        const int mt = q % nmt, kt = q / nmt;
        const int row = mt * 16 + (lane >> 2) + (r & 1) * 8;
        const int col = kt * 16 + 2 * (lane & 3) + (r >> 1) * 8;
        const int rmax = is3 ? 30 : 100;
        const float* W = is3 ? W3 : W2;
        float w0 = 0.f, w1 = 0.f;
        if (row < rmax) {
            if (col < 100)     w0 = W[row * 100 + col];
            if (col + 1 < 100) w1 = W[row * 100 + col + 1];
        }
        const unsigned p = h2pk(w0, w1);
        if (is3) g_W3f[id] = p;
        else     g_W2f[id] = p;
    }
}

// ---------------- persistent MLP kernel: 256 threads, 128 points per tile ----------------
__global__ __launch_bounds__(256, 2)
void mlp_kernel(const float* __restrict__ x, const float* __restrict__ nd,
                const float* __restrict__ W1, const float* __restrict__ b1,
                const float* __restrict__ b2, const float* __restrict__ b3,
                const float* __restrict__ W4, const float* __restrict__ b4)
{
    extern __shared__ char smraw[];
    float* Hs = (float*)(smraw + SM_HS);
    const uint4* W2F = (const uint4*)(smraw + SM_W2F);
    float* mf = (float*)(smraw + SM_MISC);

    const int tid = threadIdx.x;
    const int lane = tid & 31, warp = tid >> 5;
    const int g = lane >> 2, t = lane & 3;
    const int n0 = warp * 16;              // each warp owns 16 points (2 n-tiles of 8)

    // ---- phase 0: coalesced copy of packed W2 fragments + small params ----
    {
        uint4* dst = (uint4*)(smraw + SM_W2F);
        const uint4* src = (const uint4*)g_W2f;
        for (int i = tid; i < NW2 / 4; i += 256) dst[i] = src[i];
        for (int i = tid; i < 200; i += 256) mf[i] = W1[i];
        if (tid < 100) { mf[200 + tid] = b1[tid]; mf[300 + tid] = b2[tid]; }
        if (tid < 32)  mf[400 + tid] = (tid < 30) ? b3[tid] : 0.f;
        if (tid < 60)  mf[432 + tid] = W4[tid];
        if (tid < 2)   mf[492 + tid] = b4[tid];
    }
    __syncthreads();

    const uint4* W3f4 = (const uint4*)g_W3f;

    for (int tile = blockIdx.x; tile < NTILES; tile += GRID_MLP) {
        const int pbase = tile * 128;

        // ---- layer 1: 2 -> 100, ReLU. Two threads per point (j-halves). ----
        {
            const int p = tid & 127, half = tid >> 7;
            const int pg = pbase + p;
            float px = 0.f, py = 0.f;
            if (pg < TOTAL) {
                const float2 v = (pg < BN) ? ((const float2*)x)[pg]
                                           : ((const float2*)nd)[pg - BN];
                px = v.x; py = v.y;
            }
            const int j0 = half * 50;
            #pragma unroll 10
            for (int j = j0; j < j0 + 50; j++) {
                float v = fmaf(mf[2 * j], px, fmaf(mf[2 * j + 1], py, mf[200 + j]));
                Hs[j * NSTR + p] = fmaxf(v, 0.f);
            }
            for (int i = tid; i < 12 * NSTR; i += 256) Hs[100 * NSTR + i] = 0.f;
        }
        __syncthreads();

        // ---- layer 2: 100 -> 100 via single-product fp16 mma ----
        float C[MT2][2][4];
        #pragma unroll
        for (int mt = 0; mt < MT2; mt++)
            #pragma unroll
            for (int nt = 0; nt < 2; nt++)
                #pragma unroll
                for (int r = 0; r < 4; r++) C[mt][nt][r] = 0.f;

        for (int kt = 0; kt < KT; kt++) {
            const int k0 = kt * 16 + 2 * t;
            unsigned bf[2][2];
            #pragma unroll
            for (int nt = 0; nt < 2; nt++) {
                const int c = n0 + nt * 8 + g;
                bf[nt][0] = h2pk(Hs[(k0 + 0) * NSTR + c], Hs[(k0 + 1) * NSTR + c]);
                bf[nt][1] = h2pk(Hs[(k0 + 8) * NSTR + c], Hs[(k0 + 9) * NSTR + c]);
            }
            #pragma unroll
            for (int mt = 0; mt < MT2; mt++) {
                const uint4 a = W2F[(kt * MT2 + mt) * 32 + lane];
                mma16(C[mt][0], a, bf[0][0], bf[0][1]);
                mma16(C[mt][1], a, bf[1][0], bf[1][1]);
            }
        }
        __syncthreads();   // all layer-2 reads of Hs complete

        // write h2 = relu(C + b2) into Hs rows 0..111 (rows >=100 zeroed)
        #pragma unroll
        for (int mt = 0; mt < MT2; mt++)
            #pragma unroll
            for (int half = 0; half < 2; half++) {
                const int row = mt * 16 + g + half * 8;
                const float bias = (row < 100) ? mf[300 + row] : 0.f;
                #pragma unroll
                for (int nt = 0; nt < 2; nt++) {
                    float v0 = C[mt][nt][2 * half + 0] + bias;
                    float v1 = C[mt][nt][2 * half + 1] + bias;
                    if (row >= 100) { v0 = 0.f; v1 = 0.f; }
                    else { v0 = fmaxf(v0, 0.f); v1 = fmaxf(v1, 0.f); }
                    Hs[row * NSTR + n0 + nt * 8 + 2 * t] = v0;
                    Hs[row * NSTR + n0 + nt * 8 + 2 * t + 1] = v1;
                }
            }
        __syncthreads();

        // ---- layer 3: 100 -> 30 via single-product fp16 mma (frags from L2) ----
        float D[MT3][2][4];
        #pragma unroll
        for (int mt = 0; mt < MT3; mt++)
            #pragma unroll
            for (int nt = 0; nt < 2; nt++)
                #pragma unroll
                for (int r = 0; r < 4; r++) D[mt][nt][r] = 0.f;

        for (int kt = 0; kt < KT; kt++) {
            uint4 a3[MT3];
            #pragma unroll
            for (int mt = 0; mt < MT3; mt++)
                a3[mt] = W3f4[(kt * MT3 + mt) * 32 + lane];
            const int k0 = kt * 16 + 2 * t;
            unsigned bf[2][2];
            #pragma unroll
            for (int nt = 0; nt < 2; nt++) {
                const int c = n0 + nt * 8 + g;
                bf[nt][0] = h2pk(Hs[(k0 + 0) * NSTR + c], Hs[(k0 + 1) * NSTR + c]);
                bf[nt][1] = h2pk(Hs[(k0 + 8) * NSTR + c], Hs[(k0 + 9) * NSTR + c]);
            }
            #pragma unroll
            for (int mt = 0; mt < MT3; mt++) {
                mma16(D[mt][0], a3[mt], bf[0][0], bf[0][1]);
                mma16(D[mt][1], a3[mt], bf[1][0], bf[1][1]);
            }
        }

        // ---- layer 4: 30 -> 2 directly from D fragments, warp shuffle reduce ----
        {
            float acc[2][2][2];   // [nt][col01][out01]
            #pragma unroll
            for (int nt = 0; nt < 2; nt++)
                #pragma unroll
                for (int c2 = 0; c2 < 2; c2++) { acc[nt][c2][0] = 0.f; acc[nt][c2][1] = 0.f; }
            #pragma unroll
            for (int mt = 0; mt < MT3; mt++)
                #pragma unroll
                for (int half = 0; half < 2; half++) {
                    const int row = mt * 16 + g + half * 8;
                    const float w0 = (row < 30) ? mf[432 + row] : 0.f;   // W4[0][row]
                    const float w1 = (row < 30) ? mf[462 + row] : 0.f;   // W4[1][row]
                    const float bias = (row < 30) ? mf[400 + row] : 0.f;
                    #pragma unroll
                    for (int nt = 0; nt < 2; nt++) {
                        const float h0 = fmaxf(D[mt][nt][2 * half + 0] + bias, 0.f);
                        const float h1 = fmaxf(D[mt][nt][2 * half + 1] + bias, 0.f);
                        acc[nt][0][0] = fmaf(w0, h0, acc[nt][0][0]);
                        acc[nt][0][1] = fmaf(w1, h0, acc[nt][0][1]);
                        acc[nt][1][0] = fmaf(w0, h1, acc[nt][1][0]);
                        acc[nt][1][1] = fmaf(w1, h1, acc[nt][1][1]);
                    }
                }
            #pragma unroll
            for (int o = 4; o <= 16; o <<= 1)
                #pragma unroll
                for (int nt = 0; nt < 2; nt++)
                    #pragma unroll
                    for (int c2 = 0; c2 < 2; c2++) {
                        acc[nt][c2][0] += __shfl_xor_sync(0xffffffffu, acc[nt][c2][0], o);
                        acc[nt][c2][1] += __shfl_xor_sync(0xffffffffu, acc[nt][c2][1], o);
                    }
            if (g == 0) {   // lanes 0..3 hold final sums for their 4 point-columns
                #pragma unroll
                for (int nt = 0; nt < 2; nt++)
                    #pragma unroll
                    for (int c2 = 0; c2 < 2; c2++) {
                        const int pg = pbase + n0 + nt * 8 + 2 * t + c2;
                        if (pg < TOTAL)
                            ((float2*)g_feat)[pg] = make_float2(acc[nt][c2][0] + mf[492],
                                                                acc[nt][c2][1] + mf[493]);
                    }
            }
        }
        __syncthreads();   // Hs reads (layer 3) done before next tile's layer-1 writes
    }
}

// ---------------- routing kernel: TWO queries per block ----------------
// Both queries' idx loads issue back-to-back, then both gathers: 2x MLP on the
// latency-critical chain, half the blocks/waves.
__global__ __launch_bounds__(256)
void route_kernel(const int* __restrict__ nbr_idx, const int* __restrict__ labels,
                  float* __restrict__ out)
{
    __shared__ float p_s[2][CC];
    __shared__ float terms[2][DD - 1];

    const int b0 = blockIdx.x * 2;
    const int tid = threadIdx.x;
    const int d = tid >> 5, lane = tid & 31;

    if (tid < 2 * CC) ((float*)p_s)[tid] = 0.f;
    __syncthreads();

    // issue both index loads, then both gathers (max MLP on the chain)
    const int i0 = nbr_idx[b0 * (DD * KK) + tid];
    const int i1 = nbr_idx[(b0 + 1) * (DD * KK) + tid];
    const float2 q0 = ((const float2*)g_feat)[b0];
    const float2 q1 = ((const float2*)g_feat)[b0 + 1];
    const float2 g0 = ((const float2*)g_feat)[BN + i0];
    const float2 g1 = ((const float2*)g_feat)[BN + i1];

    const float dx0 = g0.x - q0.x + 1e-6f, dy0 = g0.y - q0.y + 1e-6f;
    const float dx1 = g1.x - q1.x + 1e-6f, dy1 = g1.y - q1.y + 1e-6f;
    const float dist0 = sqrtf(fmaf(dx0, dx0, dy0 * dy0));
    const float dist1 = sqrtf(fmaf(dx1, dx1, dy1 * dy1));

    // dist >= 0 -> IEEE bits order-preserving: u32 redux.min == max(-dist)
    const float mind0 = __uint_as_float(__reduce_min_sync(0xffffffffu, __float_as_uint(dist0)));
    const float mind1 = __uint_as_float(__reduce_min_sync(0xffffffffu, __float_as_uint(dist1)));
    const float e0 = __expf(mind0 - dist0);   // argmax lane exactly exp(0) = 1
    const float e1 = __expf(mind1 - dist1);
    float s0 = e0, s1 = e1;
    #pragma unroll
    for (int o = 16; o > 0; o >>= 1) {
        s0 += __shfl_xor_sync(0xffffffffu, s0, o);
        s1 += __shfl_xor_sync(0xffffffffu, s1, o);
    }

    if (d < DD - 1) {
        if (lane == 0) {
            terms[0][d] = __logf(__fdividef(1.0f, s0) + 1e-4f);
            terms[1][d] = __logf(__fdividef(1.0f, s1) + 1e-4f);
        }
    } else {
        const int c0 = labels[i0];
        const int c1 = labels[i1];
        atomicAdd(&p_s[0][c0], __fdividef(e0, s0));
        atomicAdd(&p_s[1][c1], __fdividef(e1, s1));
    }
    __syncthreads();

    if (tid < 2 * CC) {
        const int u = tid / CC, c = tid - u * CC;
        float tsum = terms[u][0] + terms[u][1] + terms[u][2] + terms[u][3]
                   + terms[u][4] + terms[u][5] + terms[u][6];
        out[(long)(b0 + u) * CC + c] = __logf(p_s[u][c] + 1e-4f) + tsum;
    }
}

extern "C" void kernel_launch(void* const* d_in, const int* in_sizes, int n_in,
                              void* d_out, int out_size)
{
    const float* x      = (const float*)d_in[0];
    const float* nd     = (const float*)d_in[1];
    const float* W1     = (const float*)d_in[2];
    const float* b1     = (const float*)d_in[3];
    const float* W2     = (const float*)d_in[4];
    const float* b2     = (const float*)d_in[5];
    const float* W3     = (const float*)d_in[6];
    const float* b3     = (const float*)d_in[7];
    const float* W4     = (const float*)d_in[8];
    const float* b4     = (const float*)d_in[9];
    const int*   labels = (const int*)d_in[10];
    const int*   nbr    = (const int*)d_in[11];
    float* out = (float*)d_out;

    cudaFuncSetAttribute(mlp_kernel, cudaFuncAttributeMaxDynamicSharedMemorySize, SMEM_TOTAL);

    pack_kernel<<<64, 256>>>(W2, W3);
    mlp_kernel<<<GRID_MLP, 256, SMEM_TOTAL>>>(x, nd, W1, b1, b2, b3, W4, b4);
    route_kernel<<<BN / 2, 256>>>(nbr, labels, out);
}

// round 13
// speedup vs baseline: 1.5678x; 1.0096x over previous
#include <cuda_runtime.h>
#include <cuda_fp16.h>
#include <math.h>

#define BN 8192
#define NN 100000
#define DD 8
#define KK 32
#define CC 100
#define TOTAL (BN + NN)
#define NTILES ((TOTAL + 127) / 128)   // 846
#define GRID_MLP 296                   // 2 blocks/SM persistent

#define NSTR 132          // stride mod 32 == 4 -> B-frag LDS conflict-free
#define KT   7            // k-tiles of 16 covering K=100 (pad 112)
#define MT2  7            // m-tiles of 16 covering M=100 (pad 112)
#define MT3  2            // m-tiles of 16 covering M=30  (pad 32)
#define NW2  (KT * MT2 * 128)   // 6272 u32 (each = 2 fp16)
#define NW3  (KT * MT3 * 128)   // 1792 u32

// ---- smem layout (bytes) ----
#define SM_HS    0                       // Hs fp32 [112][NSTR] = 59136
#define SM_W2F   59136                   // W2 frags: 6272 u32 = 25088
#define SM_W3F   84224                   // W3 frags: 1792 u32 = 7168
#define SM_MISC  91392                   // mf floats [494]
#define SMEM_TOTAL 93376

// Feature scratch: [0..BN) queries, [BN..TOTAL) nodes, (x,y) pairs.
__device__ float g_feat[TOTAL * 2];

__device__ __forceinline__ unsigned h2pk(float lo, float hi) {  // pack {lo, hi} as f16x2
    unsigned r;
    asm("cvt.rn.f16x2.f32 %0, %1, %2;" : "=r"(r) : "f"(hi), "f"(lo));
    return r;
}

__device__ __forceinline__ void mma16(float (&c)[4], const uint4& a, unsigned b0, unsigned b1) {
    asm("mma.sync.aligned.m16n8k16.row.col.f32.f16.f16.f32 "
        "{%0,%1,%2,%3}, {%4,%5,%6,%7}, {%8,%9}, {%0,%1,%2,%3};"
        : "+f"(c[0]), "+f"(c[1]), "+f"(c[2]), "+f"(c[3])
        : "r"(a.x), "r"(a.y), "r"(a.z), "r"(a.w), "r"(b0), "r"(b1));
}

// ---------------- persistent MLP kernel: 256 threads, 128 points per tile ----------------
__global__ __launch_bounds__(256, 2)
void mlp_kernel(const float* __restrict__ x, const float* __restrict__ nd,
                const float* __restrict__ W1, const float* __restrict__ b1,
                const float* __restrict__ W2, const float* __restrict__ b2,
                const float* __restrict__ W3, const float* __restrict__ b3,
                const float* __restrict__ W4, const float* __restrict__ b4)
{
    extern __shared__ char smraw[];
    float* Hs = (float*)(smraw + SM_HS);
    const uint4* W2F = (const uint4*)(smraw + SM_W2F);
    const uint4* W3F = (const uint4*)(smraw + SM_W3F);
    float* mf = (float*)(smraw + SM_MISC);

    const int tid = threadIdx.x;
    const int lane = tid & 31, warp = tid >> 5;
    const int g = lane >> 2, t = lane & 3;
    const int n0 = warp * 16;              // each warp owns 16 points (2 n-tiles of 8)

    // ---- phase 0: inline coalesced pack of W2/W3 into fp16 fragment smem ----
    {
        // zero both fragment regions (covers padded rows/cols)
        uint4* z = (uint4*)(smraw + SM_W2F);
        for (int i = tid; i < (25088 + 7168) / 16; i += 256) z[i] = make_uint4(0, 0, 0, 0);
        __syncthreads();

        // W2: read linearly as float4, scatter halves into fragment slots.
        // frag layout: u32 id = ((kt*MT+mt)*32 + lane)*4 + r
        //   row = mt*16 + (lane>>2) + (r&1)*8 ; col = kt*16 + 2*(lane&3) + (r>>1)*8 (+b)
        __half* W2Fh = (__half*)(smraw + SM_W2F);
        for (int i = tid; i < 2500; i += 256) {
            const float4 w = ((const float4*)W2)[i];
            const float we[4] = {w.x, w.y, w.z, w.w};
            const int base = i * 4;
            #pragma unroll
            for (int e = 0; e < 4; e++) {
                const int idx = base + e;
                const int row = idx / 100, col = idx - row * 100;
                const int mt = row >> 4, rr = row & 15;
                const int kt = col >> 4, cc = col & 15;
                const int ln = (rr & 7) * 4 + ((cc >> 1) & 3);
                const int r = (rr >> 3) + ((cc >> 3) << 1);
                const int fid = ((kt * MT2 + mt) * 32 + ln) * 4 + r;
                W2Fh[fid * 2 + (cc & 1)] = __float2half_rn(we[e]);
            }
        }
        __half* W3Fh = (__half*)(smraw + SM_W3F);
        for (int i = tid; i < 750; i += 256) {
            const float4 w = ((const float4*)W3)[i];
            const float we[4] = {w.x, w.y, w.z, w.w};
            const int base = i * 4;
            #pragma unroll
            for (int e = 0; e < 4; e++) {
                const int idx = base + e;
                const int row = idx / 100, col = idx - row * 100;
                const int mt = row >> 4, rr = row & 15;
                const int kt = col >> 4, cc = col & 15;
                const int ln = (rr & 7) * 4 + ((cc >> 1) & 3);
                const int r = (rr >> 3) + ((cc >> 3) << 1);
                const int fid = ((kt * MT3 + mt) * 32 + ln) * 4 + r;
                W3Fh[fid * 2 + (cc & 1)] = __float2half_rn(we[e]);
            }
        }
        for (int i = tid; i < 200; i += 256) mf[i] = W1[i];
        if (tid < 100) { mf[200 + tid] = b1[tid]; mf[300 + tid] = b2[tid]; }
        if (tid < 32)  mf[400 + tid] = (tid < 30) ? b3[tid] : 0.f;
        if (tid < 60)  mf[432 + tid] = W4[tid];
        if (tid < 2)   mf[492 + tid] = b4[tid];
    }
    __syncthreads();

    for (int tile = blockIdx.x; tile < NTILES; tile += GRID_MLP) {
        const int pbase = tile * 128;

        // ---- layer 1: 2 -> 100, ReLU. Two threads per point (j-halves). ----
        {
            const int p = tid & 127, half = tid >> 7;
            const int pg = pbase + p;
            float px = 0.f, py = 0.f;
            if (pg < TOTAL) {
                const float2 v = (pg < BN) ? ((const float2*)x)[pg]
                                           : ((const float2*)nd)[pg - BN];
                px = v.x; py = v.y;
            }
            const int j0 = half * 50;
            #pragma unroll 10
            for (int j = j0; j < j0 + 50; j++) {
                float v = fmaf(mf[2 * j], px, fmaf(mf[2 * j + 1], py, mf[200 + j]));
                Hs[j * NSTR + p] = fmaxf(v, 0.f);
            }
            for (int i = tid; i < 12 * NSTR; i += 256) Hs[100 * NSTR + i] = 0.f;
        }
        __syncthreads();

        // ---- layer 2: 100 -> 100 via single-product fp16 mma ----
        float C[MT2][2][4];
        #pragma unroll
        for (int mt = 0; mt < MT2; mt++)
            #pragma unroll
            for (int nt = 0; nt < 2; nt++)
                #pragma unroll
                for (int r = 0; r < 4; r++) C[mt][nt][r] = 0.f;

        for (int kt = 0; kt < KT; kt++) {
            const int k0 = kt * 16 + 2 * t;
            unsigned bf[2][2];
            #pragma unroll
            for (int nt = 0; nt < 2; nt++) {
                const int c = n0 + nt * 8 + g;
                bf[nt][0] = h2pk(Hs[(k0 + 0) * NSTR + c], Hs[(k0 + 1) * NSTR + c]);
                bf[nt][1] = h2pk(Hs[(k0 + 8) * NSTR + c], Hs[(k0 + 9) * NSTR + c]);
            }
            #pragma unroll
            for (int mt = 0; mt < MT2; mt++) {
                const uint4 a = W2F[(kt * MT2 + mt) * 32 + lane];
                mma16(C[mt][0], a, bf[0][0], bf[0][1]);
                mma16(C[mt][1], a, bf[1][0], bf[1][1]);
            }
        }
        __syncthreads();   // all layer-2 reads of Hs complete

        // write h2 = relu(C + b2) into Hs rows 0..111 (rows >=100 zeroed)
        #pragma unroll
        for (int mt = 0; mt < MT2; mt++)
            #pragma unroll
            for (int half = 0; half < 2; half++) {
                const int row = mt * 16 + g + half * 8;
                const float bias = (row < 100) ? mf[300 + row] : 0.f;
                #pragma unroll
                for (int nt = 0; nt < 2; nt++) {
                    float v0 = C[mt][nt][2 * half + 0] + bias;
                    float v1 = C[mt][nt][2 * half + 1] + bias;
                    if (row >= 100) { v0 = 0.f; v1 = 0.f; }
                    else { v0 = fmaxf(v0, 0.f); v1 = fmaxf(v1, 0.f); }
                    Hs[row * NSTR + n0 + nt * 8 + 2 * t] = v0;
                    Hs[row * NSTR + n0 + nt * 8 + 2 * t + 1] = v1;
                }
            }
        __syncthreads();

        // ---- layer 3: 100 -> 30 via single-product fp16 mma (frags from SMEM) ----
        float D[MT3][2][4];
        #pragma unroll
        for (int mt = 0; mt < MT3; mt++)
            #pragma unroll
            for (int nt = 0; nt < 2; nt++)
                #pragma unroll
                for (int r = 0; r < 4; r++) D[mt][nt][r] = 0.f;

        for (int kt = 0; kt < KT; kt++) {
            const int k0 = kt * 16 + 2 * t;
            unsigned bf[2][2];
            #pragma unroll
            for (int nt = 0; nt < 2; nt++) {
                const int c = n0 + nt * 8 + g;
                bf[nt][0] = h2pk(Hs[(k0 + 0) * NSTR + c], Hs[(k0 + 1) * NSTR + c]);
                bf[nt][1] = h2pk(Hs[(k0 + 8) * NSTR + c], Hs[(k0 + 9) * NSTR + c]);
            }
            #pragma unroll
            for (int mt = 0; mt < MT3; mt++) {
                const uint4 a = W3F[(kt * MT3 + mt) * 32 + lane];
                mma16(D[mt][0], a, bf[0][0], bf[0][1]);
                mma16(D[mt][1], a, bf[1][0], bf[1][1]);
            }
        }

        // ---- layer 4: 30 -> 2 directly from D fragments, warp shuffle reduce ----
        {
            float acc[2][2][2];   // [nt][col01][out01]
            #pragma unroll
            for (int nt = 0; nt < 2; nt++)
                #pragma unroll
                for (int c2 = 0; c2 < 2; c2++) { acc[nt][c2][0] = 0.f; acc[nt][c2][1] = 0.f; }
            #pragma unroll
            for (int mt = 0; mt < MT3; mt++)
                #pragma unroll
                for (int half = 0; half < 2; half++) {
                    const int row = mt * 16 + g + half * 8;
                    const float w0 = (row < 30) ? mf[432 + row] : 0.f;   // W4[0][row]
                    const float w1 = (row < 30) ? mf[462 + row] : 0.f;   // W4[1][row]
                    const float bias = (row < 30) ? mf[400 + row] : 0.f;
                    #pragma unroll
                    for (int nt = 0; nt < 2; nt++) {
                        const float h0 = fmaxf(D[mt][nt][2 * half + 0] + bias, 0.f);
                        const float h1 = fmaxf(D[mt][nt][2 * half + 1] + bias, 0.f);
                        acc[nt][0][0] = fmaf(w0, h0, acc[nt][0][0]);
                        acc[nt][0][1] = fmaf(w1, h0, acc[nt][0][1]);
                        acc[nt][1][0] = fmaf(w0, h1, acc[nt][1][0]);
                        acc[nt][1][1] = fmaf(w1, h1, acc[nt][1][1]);
                    }
                }
            #pragma unroll
            for (int o = 4; o <= 16; o <<= 1)
                #pragma unroll
                for (int nt = 0; nt < 2; nt++)
                    #pragma unroll
                    for (int c2 = 0; c2 < 2; c2++) {
                        acc[nt][c2][0] += __shfl_xor_sync(0xffffffffu, acc[nt][c2][0], o);
                        acc[nt][c2][1] += __shfl_xor_sync(0xffffffffu, acc[nt][c2][1], o);
                    }
            if (g == 0) {   // lanes 0..3 hold final sums for their 4 point-columns
                #pragma unroll
                for (int nt = 0; nt < 2; nt++)
                    #pragma unroll
                    for (int c2 = 0; c2 < 2; c2++) {
                        const int pg = pbase + n0 + nt * 8 + 2 * t + c2;
                        if (pg < TOTAL)
                            ((float2*)g_feat)[pg] = make_float2(acc[nt][c2][0] + mf[492],
                                                                acc[nt][c2][1] + mf[493]);
                    }
            }
        }
        __syncthreads();   // Hs reads (layer 3) done before next tile's layer-1 writes
    }
}

// ---------------- routing kernel: FOUR queries per block ----------------
__global__ __launch_bounds__(256)
void route_kernel(const int* __restrict__ nbr_idx, const int* __restrict__ labels,
                  float* __restrict__ out)
{
    __shared__ float p_s[4][CC];
    __shared__ float terms[4][DD - 1];

    const int b0 = blockIdx.x * 4;
    const int tid = threadIdx.x;
    const int d = tid >> 5, lane = tid & 31;

    for (int i = tid; i < 4 * CC; i += 256) ((float*)p_s)[i] = 0.f;
    __syncthreads();

    // issue all 4 index loads, then all 4 gathers (max MLP on the chain)
    int idx4[4];
    #pragma unroll
    for (int u = 0; u < 4; u++) idx4[u] = nbr_idx[(b0 + u) * (DD * KK) + tid];
    float2 q4[4], g4[4];
    #pragma unroll
    for (int u = 0; u < 4; u++) q4[u] = ((const float2*)g_feat)[b0 + u];
    #pragma unroll
    for (int u = 0; u < 4; u++) g4[u] = ((const float2*)g_feat)[BN + idx4[u]];

    float e4[4], s4[4];
    #pragma unroll
    for (int u = 0; u < 4; u++) {
        const float dx = g4[u].x - q4[u].x + 1e-6f;
        const float dy = g4[u].y - q4[u].y + 1e-6f;
        const float dist = sqrtf(fmaf(dx, dx, dy * dy));
        // dist >= 0 -> IEEE bits order-preserving: u32 redux.min == max(-dist)
        const float mind = __uint_as_float(__reduce_min_sync(0xffffffffu, __float_as_uint(dist)));
        e4[u] = __expf(mind - dist);   // argmax lane exactly exp(0) = 1
        s4[u] = e4[u];
    }
    #pragma unroll
    for (int o = 16; o > 0; o >>= 1)
        #pragma unroll
        for (int u = 0; u < 4; u++) s4[u] += __shfl_xor_sync(0xffffffffu, s4[u], o);

    if (d < DD - 1) {
        if (lane == 0) {
            #pragma unroll
            for (int u = 0; u < 4; u++)
                terms[u][d] = __logf(__fdividef(1.0f, s4[u]) + 1e-4f);
        }
    } else {
        #pragma unroll
        for (int u = 0; u < 4; u++) {
            const int c = labels[idx4[u]];
            atomicAdd(&p_s[u][c], __fdividef(e4[u], s4[u]));
        }
    }
    __syncthreads();

    for (int i = tid; i < 4 * CC; i += 256) {
        const int u = i / CC, c = i - u * CC;
        float tsum = terms[u][0] + terms[u][1] + terms[u][2] + terms[u][3]
                   + terms[u][4] + terms[u][5] + terms[u][6];
        out[(long)(b0 + u) * CC + c] = __logf(p_s[u][c] + 1e-4f) + tsum;
    }
}

extern "C" void kernel_launch(void* const* d_in, const int* in_sizes, int n_in,
                              void* d_out, int out_size)
{
    const float* x      = (const float*)d_in[0];
    const float* nd     = (const float*)d_in[1];
    const float* W1     = (const float*)d_in[2];
    const float* b1     = (const float*)d_in[3];
    const float* W2     = (const float*)d_in[4];
    const float* b2     = (const float*)d_in[5];
    const float* W3     = (const float*)d_in[6];
    const float* b3     = (const float*)d_in[7];
    const float* W4     = (const float*)d_in[8];
    const float* b4     = (const float*)d_in[9];
    const int*   labels = (const int*)d_in[10];
    const int*   nbr    = (const int*)d_in[11];
    float* out = (float*)d_out;

    cudaFuncSetAttribute(mlp_kernel, cudaFuncAttributeMaxDynamicSharedMemorySize, SMEM_TOTAL);

    mlp_kernel<<<GRID_MLP, 256, SMEM_TOTAL>>>(x, nd, W1, b1, W2, b2, W3, b3, W4, b4);
    route_kernel<<<BN / 4, 256>>>(nbr, labels, out);
}

// round 14
// speedup vs baseline: 1.5713x; 1.0022x over previous
#include <cuda_runtime.h>
#include <cuda_fp16.h>
#include <math.h>

#define BN 8192
#define NN 100000
#define DD 8
#define KK 32
#define CC 100
#define TOTAL (BN + NN)
#define NTILES ((TOTAL + 127) / 128)   // 846
#define GRID_MLP 296                   // 2 blocks/SM persistent

#define KT   7            // k-tiles of 16 covering K=100 (pad 112)
#define MT2  7            // m-tiles of 16 covering M=100 (pad 112)
#define MT3  2            // m-tiles of 16 covering M=30  (pad 32)
#define NW2  (KT * MT2 * 128)   // 6272 u32 (each = 2 fp16)
#define NW3  (KT * MT3 * 128)   // 1792 u32

#define NSH  68           // words per point in Hs16 (136 fp16; 68 % 32 == 4 -> conflict-free B frags)

// ---- smem layout (bytes) ----
#define SM_HS    0                       // Hs16: 128 points * 68 u32 = 34816
#define SM_W2F   34816                   // W2 frags: 25088
#define SM_W3F   59904                   // W3 frags: 7168
#define SM_MISC  67072                   // mf floats [494]
#define SMEM_TOTAL 69120

// Feature scratch: [0..BN) queries, [BN..TOTAL) nodes, (x,y) pairs.
__device__ float g_feat[TOTAL * 2];

__device__ __forceinline__ unsigned h2pk(float lo, float hi) {  // u32 = {lo:lo, hi:hi}
    unsigned r;
    asm("cvt.rn.f16x2.f32 %0, %1, %2;" : "=r"(r) : "f"(hi), "f"(lo));
    return r;
}

__device__ __forceinline__ void mma16(float (&c)[4], const uint4& a, unsigned b0, unsigned b1) {
    asm("mma.sync.aligned.m16n8k16.row.col.f32.f16.f16.f32 "
        "{%0,%1,%2,%3}, {%4,%5,%6,%7}, {%8,%9}, {%0,%1,%2,%3};"
        : "+f"(c[0]), "+f"(c[1]), "+f"(c[2]), "+f"(c[3])
        : "r"(a.x), "r"(a.y), "r"(a.z), "r"(a.w), "r"(b0), "r"(b1));
}

// ---------------- persistent MLP kernel: 256 threads, 128 points per tile ----------------
__global__ __launch_bounds__(256, 2)
void mlp_kernel(const float* __restrict__ x, const float* __restrict__ nd,
                const float* __restrict__ W1, const float* __restrict__ b1,
                const float* __restrict__ W2, const float* __restrict__ b2,
                const float* __restrict__ W3, const float* __restrict__ b3,
                const float* __restrict__ W4, const float* __restrict__ b4)
{
    extern __shared__ char smraw[];
    unsigned* HsW = (unsigned*)(smraw + SM_HS);     // [point][kword]
    __half*   Hsh = (__half*)(smraw + SM_HS);       // [point][k]
    const uint4* W2F = (const uint4*)(smraw + SM_W2F);
    const uint4* W3F = (const uint4*)(smraw + SM_W3F);
    float* mf = (float*)(smraw + SM_MISC);

    const int tid = threadIdx.x;
    const int lane = tid & 31, warp = tid >> 5;
    const int g = lane >> 2, t = lane & 3;
    const int n0 = warp * 16;              // each warp owns 16 points (2 n-tiles of 8)

    // ---- phase 0: zero Hs+frag regions, inline coalesced pack of W2/W3, params ----
    {
        uint4* z = (uint4*)smraw;
        for (int i = tid; i < SM_MISC / 16; i += 256) z[i] = make_uint4(0, 0, 0, 0);
        __syncthreads();

        // frag layout: u32 id = ((kt*MT+mt)*32 + ln)*4 + r
        //   row = mt*16 + (ln>>2) + (r&1)*8 ; col = kt*16 + 2*(ln&3) + (r>>1)*8 (+b)
        __half* W2Fh = (__half*)(smraw + SM_W2F);
        for (int i = tid; i < 2500; i += 256) {
            const float4 w = ((const float4*)W2)[i];
            const float we[4] = {w.x, w.y, w.z, w.w};
            const int base = i * 4;
            #pragma unroll
            for (int e = 0; e < 4; e++) {
                const int idx = base + e;
                const int row = idx / 100, col = idx - row * 100;
                const int mt = row >> 4, rr = row & 15;
                const int kt = col >> 4, cc = col & 15;
                const int ln = (rr & 7) * 4 + ((cc >> 1) & 3);
                const int r = (rr >> 3) + ((cc >> 3) << 1);
                const int fid = ((kt * MT2 + mt) * 32 + ln) * 4 + r;
                W2Fh[fid * 2 + (cc & 1)] = __float2half_rn(we[e]);
            }
        }
        __half* W3Fh = (__half*)(smraw + SM_W3F);
        for (int i = tid; i < 750; i += 256) {
            const float4 w = ((const float4*)W3)[i];
            const float we[4] = {w.x, w.y, w.z, w.w};
            const int base = i * 4;
            #pragma unroll
            for (int e = 0; e < 4; e++) {
                const int idx = base + e;
                const int row = idx / 100, col = idx - row * 100;
                const int mt = row >> 4, rr = row & 15;
                const int kt = col >> 4, cc = col & 15;
                const int ln = (rr & 7) * 4 + ((cc >> 1) & 3);
                const int r = (rr >> 3) + ((cc >> 3) << 1);
                const int fid = ((kt * MT3 + mt) * 32 + ln) * 4 + r;
                W3Fh[fid * 2 + (cc & 1)] = __float2half_rn(we[e]);
            }
        }
        for (int i = tid; i < 200; i += 256) mf[i] = W1[i];
        if (tid < 100) { mf[200 + tid] = b1[tid]; mf[300 + tid] = b2[tid]; }
        if (tid < 32)  mf[400 + tid] = (tid < 30) ? b3[tid] : 0.f;
        if (tid < 60)  mf[432 + tid] = W4[tid];
        if (tid < 2)   mf[492 + tid] = b4[tid];
    }
    __syncthreads();

    for (int tile = blockIdx.x; tile < NTILES; tile += GRID_MLP) {
        const int pbase = tile * 128;

        // ---- layer 1: 2 -> 100, ReLU, packed fp16 pair writes. 2 threads/point. ----
        {
            const int p = tid & 127, half = tid >> 7;
            const int pg = pbase + p;
            float px = 0.f, py = 0.f;
            if (pg < TOTAL) {
                const float2 v = (pg < BN) ? ((const float2*)x)[pg]
                                           : ((const float2*)nd)[pg - BN];
                px = v.x; py = v.y;
            }
            const int j0 = half * 50;
            unsigned* dst = HsW + p * NSH + (j0 >> 1);
            #pragma unroll 5
            for (int j2 = 0; j2 < 25; j2++) {
                const int j = j0 + 2 * j2;
                const float v0 = fmaxf(fmaf(mf[2 * j], px,
                                       fmaf(mf[2 * j + 1], py, mf[200 + j])), 0.f);
                const float v1 = fmaxf(fmaf(mf[2 * j + 2], px,
                                       fmaf(mf[2 * j + 3], py, mf[201 + j])), 0.f);
                dst[j2] = h2pk(v0, v1);
            }
            // k-words 50..55 (k 100..111) stay zero: zeroed at init, re-zeroed by epilogue
        }
        __syncthreads();

        // ---- layer 2: 100 -> 100 via single-product fp16 mma, 1-LDS B frags ----
        float C[MT2][2][4];
        #pragma unroll
        for (int mt = 0; mt < MT2; mt++)
            #pragma unroll
            for (int nt = 0; nt < 2; nt++)
                #pragma unroll
                for (int r = 0; r < 4; r++) C[mt][nt][r] = 0.f;

        const unsigned* b0p = HsW + (n0 + g) * NSH + t;
        const unsigned* b1p = HsW + (n0 + 8 + g) * NSH + t;
        for (int kt = 0; kt < KT; kt++) {
            const int kw = kt * 8;
            unsigned bf[2][2];
            bf[0][0] = b0p[kw];     bf[0][1] = b0p[kw + 4];
            bf[1][0] = b1p[kw];     bf[1][1] = b1p[kw + 4];
            #pragma unroll
            for (int mt = 0; mt < MT2; mt++) {
                const uint4 a = W2F[(kt * MT2 + mt) * 32 + lane];
                mma16(C[mt][0], a, bf[0][0], bf[0][1]);
                mma16(C[mt][1], a, bf[1][0], bf[1][1]);
            }
        }
        __syncthreads();   // all layer-2 reads of Hs complete

        // write h2 = relu(C + b2) as fp16 into Hs rows(features) 0..111 (>=100 zeroed)
        #pragma unroll
        for (int mt = 0; mt < MT2; mt++)
            #pragma unroll
            for (int half = 0; half < 2; half++) {
                const int row = mt * 16 + g + half * 8;
                const float bias = (row < 100) ? mf[300 + row] : 0.f;
                #pragma unroll
                for (int nt = 0; nt < 2; nt++) {
                    float v0 = C[mt][nt][2 * half + 0] + bias;
                    float v1 = C[mt][nt][2 * half + 1] + bias;
                    if (row >= 100) { v0 = 0.f; v1 = 0.f; }
                    else { v0 = fmaxf(v0, 0.f); v1 = fmaxf(v1, 0.f); }
                    const int p0 = n0 + nt * 8 + 2 * t;
                    Hsh[p0 * (2 * NSH) + row] = __float2half_rn(v0);
                    Hsh[(p0 + 1) * (2 * NSH) + row] = __float2half_rn(v1);
                }
            }
        __syncthreads();

        // ---- layer 3: 100 -> 30 via single-product fp16 mma ----
        float D[MT3][2][4];
        #pragma unroll
        for (int mt = 0; mt < MT3; mt++)
            #pragma unroll
            for (int nt = 0; nt < 2; nt++)
                #pragma unroll
                for (int r = 0; r < 4; r++) D[mt][nt][r] = 0.f;

        for (int kt = 0; kt < KT; kt++) {
            const int kw = kt * 8;
            unsigned bf[2][2];
            bf[0][0] = b0p[kw];     bf[0][1] = b0p[kw + 4];
            bf[1][0] = b1p[kw];     bf[1][1] = b1p[kw + 4];
            #pragma unroll
            for (int mt = 0; mt < MT3; mt++) {
                const uint4 a = W3F[(kt * MT3 + mt) * 32 + lane];
                mma16(D[mt][0], a, bf[0][0], bf[0][1]);
                mma16(D[mt][1], a, bf[1][0], bf[1][1]);
            }
        }

        // ---- layer 4: 30 -> 2 directly from D fragments, warp shuffle reduce ----
        {
            float acc[2][2][2];   // [nt][col01][out01]
            #pragma unroll
            for (int nt = 0; nt < 2; nt++)
                #pragma unroll
                for (int c2 = 0; c2 < 2; c2++) { acc[nt][c2][0] = 0.f; acc[nt][c2][1] = 0.f; }
            #pragma unroll
            for (int mt = 0; mt < MT3; mt++)
                #pragma unroll
                for (int half = 0; half < 2; half++) {
                    const int row = mt * 16 + g + half * 8;
                    const float w0 = (row < 30) ? mf[432 + row] : 0.f;   // W4[0][row]
                    const float w1 = (row < 30) ? mf[462 + row] : 0.f;   // W4[1][row]
                    const float bias = (row < 30) ? mf[400 + row] : 0.f;
                    #pragma unroll
                    for (int nt = 0; nt < 2; nt++) {
                        const float h0 = fmaxf(D[mt][nt][2 * half + 0] + bias, 0.f);
                        const float h1 = fmaxf(D[mt][nt][2 * half + 1] + bias, 0.f);
                        acc[nt][0][0] = fmaf(w0, h0, acc[nt][0][0]);
                        acc[nt][0][1] = fmaf(w1, h0, acc[nt][0][1]);
                        acc[nt][1][0] = fmaf(w0, h1, acc[nt][1][0]);
                        acc[nt][1][1] = fmaf(w1, h1, acc[nt][1][1]);
                    }
                }
            #pragma unroll
            for (int o = 4; o <= 16; o <<= 1)
                #pragma unroll
                for (int nt = 0; nt < 2; nt++)
                    #pragma unroll
                    for (int c2 = 0; c2 < 2; c2++) {
                        acc[nt][c2][0] += __shfl_xor_sync(0xffffffffu, acc[nt][c2][0], o);
                        acc[nt][c2][1] += __shfl_xor_sync(0xffffffffu, acc[nt][c2][1], o);
                    }
            if (g == 0) {   // lanes 0..3 hold final sums for their 4 point-columns
                #pragma unroll
                for (int nt = 0; nt < 2; nt++)
                    #pragma unroll
                    for (int c2 = 0; c2 < 2; c2++) {
                        const int pg = pbase + n0 + nt * 8 + 2 * t + c2;
                        if (pg < TOTAL)
                            ((float2*)g_feat)[pg] = make_float2(acc[nt][c2][0] + mf[492],
                                                                acc[nt][c2][1] + mf[493]);
                    }
            }
        }
        __syncthreads();   // Hs reads (layer 3) done before next tile's layer-1 writes
    }
}

// ---------------- routing kernel: FOUR queries per block ----------------
__global__ __launch_bounds__(256)
void route_kernel(const int* __restrict__ nbr_idx, const int* __restrict__ labels,
                  float* __restrict__ out)
{
    __shared__ float p_s[4][CC];
    __shared__ float terms[4][DD - 1];

    const int b0 = blockIdx.x * 4;
    const int tid = threadIdx.x;
    const int d = tid >> 5, lane = tid & 31;

    // only warp 7 (d == DD-1) touches p_s: it inits its own region, no block sync needed
    if (d == DD - 1) {
        for (int i = lane; i < 4 * CC; i += 32) ((float*)p_s)[i] = 0.f;
        __syncwarp();
    }

    // issue all 4 index loads, then all 4 gathers (max MLP on the chain)
    int idx4[4];
    #pragma unroll
    for (int u = 0; u < 4; u++) idx4[u] = nbr_idx[(b0 + u) * (DD * KK) + tid];
    float2 q4[4], g4[4];
    #pragma unroll
    for (int u = 0; u < 4; u++) q4[u] = ((const float2*)g_feat)[b0 + u];
    #pragma unroll
    for (int u = 0; u < 4; u++) g4[u] = ((const float2*)g_feat)[BN + idx4[u]];

    float e4[4], s4[4];
    #pragma unroll
    for (int u = 0; u < 4; u++) {
        const float dx = g4[u].x - q4[u].x + 1e-6f;
        const float dy = g4[u].y - q4[u].y + 1e-6f;
        const float dist = sqrtf(fmaf(dx, dx, dy * dy));
        // dist >= 0 -> IEEE bits order-preserving: u32 redux.min == max(-dist)
        const float mind = __uint_as_float(__reduce_min_sync(0xffffffffu, __float_as_uint(dist)));
        e4[u] = __expf(mind - dist);   // argmax lane exactly exp(0) = 1
        s4[u] = e4[u];
    }
    #pragma unroll
    for (int o = 16; o > 0; o >>= 1)
        #pragma unroll
        for (int u = 0; u < 4; u++) s4[u] += __shfl_xor_sync(0xffffffffu, s4[u], o);

    if (d < DD - 1) {
        if (lane == 0) {
            #pragma unroll
            for (int u = 0; u < 4; u++)
                terms[u][d] = __logf(__fdividef(1.0f, s4[u]) + 1e-4f);
        }
    } else {
        #pragma unroll
        for (int u = 0; u < 4; u++) {
            const int c = labels[idx4[u]];
            atomicAdd(&p_s[u][c], __fdividef(e4[u], s4[u]));
        }
    }
    __syncthreads();

    for (int i = tid; i < 4 * CC; i += 256) {
        const int u = i / CC, c = i - u * CC;
        float tsum = terms[u][0] + terms[u][1] + terms[u][2] + terms[u][3]
                   + terms[u][4] + terms[u][5] + terms[u][6];
        out[(long)(b0 + u) * CC + c] = __logf(p_s[u][c] + 1e-4f) + tsum;
    }
}

extern "C" void kernel_launch(void* const* d_in, const int* in_sizes, int n_in,
                              void* d_out, int out_size)
{
    const float* x      = (const float*)d_in[0];
    const float* nd     = (const float*)d_in[1];
    const float* W1     = (const float*)d_in[2];
    const float* b1     = (const float*)d_in[3];
    const float* W2     = (const float*)d_in[4];
    const float* b2     = (const float*)d_in[5];
    const float* W3     = (const float*)d_in[6];
    const float* b3     = (const float*)d_in[7];
    const float* W4     = (const float*)d_in[8];
    const float* b4     = (const float*)d_in[9];
    const int*   labels = (const int*)d_in[10];
    const int*   nbr    = (const int*)d_in[11];
    float* out = (float*)d_out;

    cudaFuncSetAttribute(mlp_kernel, cudaFuncAttributeMaxDynamicSharedMemorySize, SMEM_TOTAL);

    mlp_kernel<<<GRID_MLP, 256, SMEM_TOTAL>>>(x, nd, W1, b1, W2, b2, W3, b3, W4, b4);
    route_kernel<<<BN / 4, 256>>>(nbr, labels, out);
}

// round 15
// speedup vs baseline: 1.6232x; 1.0330x over previous
#include <cuda_runtime.h>
#include <cuda_fp16.h>
#include <math.h>

#define BN 8192
#define NN 100000
#define DD 8
#define KK 32
#define CC 100
#define TOTAL (BN + NN)
#define NTILES ((TOTAL + 127) / 128)   // 846
#define GRID_MLP 296                   // 2 blocks/SM persistent

#define KT   7            // k-tiles of 16 covering K=100 (pad 112)
#define MT2  7            // m-tiles of 16 covering M=100 (pad 112)
#define MT3  2            // m-tiles of 16 covering M=30  (pad 32)

#define NSH  68           // u32 words per point (136 fp16; 68 % 32 == 4 -> conflict-free B frags)

// ---- smem layout (bytes) ----
#define SM_H1    0                       // h1: 128 points * 68 u32 = 34816
#define SM_H2    34816                   // h2: 34816  (separate region -> fewer barriers)
#define SM_W2F   69632                   // W2 frags: 25088
#define SM_W3F   94720                   // W3 frags: 7168
#define SM_MISC  101888                  // mf floats [494]
#define SMEM_TOTAL 103936                // x2 blocks = 207.9K <= 228K per SM

// Feature scratch: [0..BN) queries, [BN..TOTAL) nodes, (x,y) pairs.
__device__ float g_feat[TOTAL * 2];

__device__ __forceinline__ unsigned h2pk(float lo, float hi) {  // u32 = {lo:lo, hi:hi}
    unsigned r;
    asm("cvt.rn.f16x2.f32 %0, %1, %2;" : "=r"(r) : "f"(hi), "f"(lo));
    return r;
}

__device__ __forceinline__ void mma16(float (&c)[4], const uint4& a, unsigned b0, unsigned b1) {
    asm("mma.sync.aligned.m16n8k16.row.col.f32.f16.f16.f32 "
        "{%0,%1,%2,%3}, {%4,%5,%6,%7}, {%8,%9}, {%0,%1,%2,%3};"
        : "+f"(c[0]), "+f"(c[1]), "+f"(c[2]), "+f"(c[3])
        : "r"(a.x), "r"(a.y), "r"(a.z), "r"(a.w), "r"(b0), "r"(b1));
}

// ---------------- persistent MLP kernel: 256 threads, 128 points per tile ----------------
__global__ __launch_bounds__(256, 2)
void mlp_kernel(const float* __restrict__ x, const float* __restrict__ nd,
                const float* __restrict__ W1, const float* __restrict__ b1,
                const float* __restrict__ W2, const float* __restrict__ b2,
                const float* __restrict__ W3, const float* __restrict__ b3,
                const float* __restrict__ W4, const float* __restrict__ b4)
{
    extern __shared__ char smraw[];
    unsigned* H1W = (unsigned*)(smraw + SM_H1);     // [point][kword] fp16x2
    unsigned* H2W = (unsigned*)(smraw + SM_H2);
    __half*   H2h = (__half*)(smraw + SM_H2);
    const uint4* W2F = (const uint4*)(smraw + SM_W2F);
    const uint4* W3F = (const uint4*)(smraw + SM_W3F);
    float* mf = (float*)(smraw + SM_MISC);

    const int tid = threadIdx.x;
    const int lane = tid & 31, warp = tid >> 5;
    const int g = lane >> 2, t = lane & 3;
    const int n0 = warp * 16;              // each warp owns 16 points (2 n-tiles of 8)

    // ---- phase 0: zero smem, inline coalesced pack of W2/W3, params ----
    {
        uint4* z = (uint4*)smraw;
        for (int i = tid; i < SM_MISC / 16; i += 256) z[i] = make_uint4(0, 0, 0, 0);
        __syncthreads();

        // frag layout: u32 id = ((kt*MT+mt)*32 + ln)*4 + r
        //   row = mt*16 + (ln>>2) + (r&1)*8 ; col = kt*16 + 2*(ln&3) + (r>>1)*8 (+b)
        __half* W2Fh = (__half*)(smraw + SM_W2F);
        for (int i = tid; i < 2500; i += 256) {
            const float4 w = ((const float4*)W2)[i];
            const float we[4] = {w.x, w.y, w.z, w.w};
            const int base = i * 4;
            #pragma unroll
            for (int e = 0; e < 4; e++) {
                const int idx = base + e;
                const int row = idx / 100, col = idx - row * 100;
                const int mt = row >> 4, rr = row & 15;
                const int kt = col >> 4, cc = col & 15;
                const int ln = (rr & 7) * 4 + ((cc >> 1) & 3);
                const int r = (rr >> 3) + ((cc >> 3) << 1);
                const int fid = ((kt * MT2 + mt) * 32 + ln) * 4 + r;
                W2Fh[fid * 2 + (cc & 1)] = __float2half_rn(we[e]);
            }
        }
        __half* W3Fh = (__half*)(smraw + SM_W3F);
        for (int i = tid; i < 750; i += 256) {
            const float4 w = ((const float4*)W3)[i];
            const float we[4] = {w.x, w.y, w.z, w.w};
            const int base = i * 4;
            #pragma unroll
            for (int e = 0; e < 4; e++) {
                const int idx = base + e;
                const int row = idx / 100, col = idx - row * 100;
                const int mt = row >> 4, rr = row & 15;
                const int kt = col >> 4, cc = col & 15;
                const int ln = (rr & 7) * 4 + ((cc >> 1) & 3);
                const int r = (rr >> 3) + ((cc >> 3) << 1);
                const int fid = ((kt * MT3 + mt) * 32 + ln) * 4 + r;
                W3Fh[fid * 2 + (cc & 1)] = __float2half_rn(we[e]);
            }
        }
        for (int i = tid; i < 200; i += 256) mf[i] = W1[i];
        if (tid < 100) { mf[200 + tid] = b1[tid]; mf[300 + tid] = b2[tid]; }
        if (tid < 32)  mf[400 + tid] = (tid < 30) ? b3[tid] : 0.f;
        if (tid < 60)  mf[432 + tid] = W4[tid];
        if (tid < 2)   mf[492 + tid] = b4[tid];
    }
    __syncthreads();

    for (int tile = blockIdx.x; tile < NTILES; tile += GRID_MLP) {
        const int pbase = tile * 128;

        // ---- layer 1: 2 -> 100, ReLU, packed fp16 pairs -> H1. 2 threads/point. ----
        // Safe w.r.t. previous tile: layer-2 H1 reads preceded last tile's sync(2).
        {
            const int p = tid & 127, half = tid >> 7;
            const int pg = pbase + p;
            float px = 0.f, py = 0.f;
            if (pg < TOTAL) {
                const float2 v = (pg < BN) ? ((const float2*)x)[pg]
                                           : ((const float2*)nd)[pg - BN];
                px = v.x; py = v.y;
            }
            const int j0 = half * 50;
            unsigned* dst = H1W + p * NSH + (j0 >> 1);
            #pragma unroll 5
            for (int j2 = 0; j2 < 25; j2++) {
                const int j = j0 + 2 * j2;
                const float v0 = fmaxf(fmaf(mf[2 * j], px,
                                       fmaf(mf[2 * j + 1], py, mf[200 + j])), 0.f);
                const float v1 = fmaxf(fmaf(mf[2 * j + 2], px,
                                       fmaf(mf[2 * j + 3], py, mf[201 + j])), 0.f);
                dst[j2] = h2pk(v0, v1);
            }
        }
        __syncthreads();   // sync(1): H1 ready; also orders prev tile's H2 reads before epi below

        // ---- layer 2: 100 -> 100 via fp16 mma reading H1 ----
        float C[MT2][2][4];
        #pragma unroll
        for (int mt = 0; mt < MT2; mt++)
            #pragma unroll
            for (int nt = 0; nt < 2; nt++)
                #pragma unroll
                for (int r = 0; r < 4; r++) C[mt][nt][r] = 0.f;

        const unsigned* a0p = H1W + (n0 + g) * NSH + t;
        const unsigned* a1p = H1W + (n0 + 8 + g) * NSH + t;
        for (int kt = 0; kt < KT; kt++) {
            const int kw = kt * 8;
            unsigned bf[2][2];
            bf[0][0] = a0p[kw];     bf[0][1] = a0p[kw + 4];
            bf[1][0] = a1p[kw];     bf[1][1] = a1p[kw + 4];
            #pragma unroll
            for (int mt = 0; mt < MT2; mt++) {
                const uint4 a = W2F[(kt * MT2 + mt) * 32 + lane];
                mma16(C[mt][0], a, bf[0][0], bf[0][1]);
                mma16(C[mt][1], a, bf[1][0], bf[1][1]);
            }
        }

        // epilogue: h2 = relu(C + b2) -> H2 (disjoint region; no barrier needed vs layer2)
        #pragma unroll
        for (int mt = 0; mt < MT2; mt++)
            #pragma unroll
            for (int half = 0; half < 2; half++) {
                const int row = mt * 16 + g + half * 8;
                const float bias = (row < 100) ? mf[300 + row] : 0.f;
                #pragma unroll
                for (int nt = 0; nt < 2; nt++) {
                    float v0 = C[mt][nt][2 * half + 0] + bias;
                    float v1 = C[mt][nt][2 * half + 1] + bias;
                    if (row >= 100) { v0 = 0.f; v1 = 0.f; }
                    else { v0 = fmaxf(v0, 0.f); v1 = fmaxf(v1, 0.f); }
                    const int p0 = n0 + nt * 8 + 2 * t;
                    H2h[p0 * (2 * NSH) + row] = __float2half_rn(v0);
                    H2h[(p0 + 1) * (2 * NSH) + row] = __float2half_rn(v1);
                }
            }
        __syncthreads();   // sync(2): H2 ready; also frees H1 for next tile's layer 1

        // ---- layer 3: 100 -> 30 via fp16 mma reading H2 ----
        float D[MT3][2][4];
        #pragma unroll
        for (int mt = 0; mt < MT3; mt++)
            #pragma unroll
            for (int nt = 0; nt < 2; nt++)
                #pragma unroll
                for (int r = 0; r < 4; r++) D[mt][nt][r] = 0.f;

        const unsigned* c0p = H2W + (n0 + g) * NSH + t;
        const unsigned* c1p = H2W + (n0 + 8 + g) * NSH + t;
        for (int kt = 0; kt < KT; kt++) {
            const int kw = kt * 8;
            unsigned bf[2][2];
            bf[0][0] = c0p[kw];     bf[0][1] = c0p[kw + 4];
            bf[1][0] = c1p[kw];     bf[1][1] = c1p[kw + 4];
            #pragma unroll
            for (int mt = 0; mt < MT3; mt++) {
                const uint4 a = W3F[(kt * MT3 + mt) * 32 + lane];
                mma16(D[mt][0], a, bf[0][0], bf[0][1]);
                mma16(D[mt][1], a, bf[1][0], bf[1][1]);
            }
        }

        // ---- layer 4: 30 -> 2 directly from D fragments, warp shuffle reduce ----
        {
            float acc[2][2][2];   // [nt][col01][out01]
            #pragma unroll
            for (int nt = 0; nt < 2; nt++)
                #pragma unroll
                for (int c2 = 0; c2 < 2; c2++) { acc[nt][c2][0] = 0.f; acc[nt][c2][1] = 0.f; }
            #pragma unroll
            for (int mt = 0; mt < MT3; mt++)
                #pragma unroll
                for (int half = 0; half < 2; half++) {
                    const int row = mt * 16 + g + half * 8;
                    const float w0 = (row < 30) ? mf[432 + row] : 0.f;   // W4[0][row]
                    const float w1 = (row < 30) ? mf[462 + row] : 0.f;   // W4[1][row]
                    const float bias = (row < 30) ? mf[400 + row] : 0.f;
                    #pragma unroll
                    for (int nt = 0; nt < 2; nt++) {
                        const float h0 = fmaxf(D[mt][nt][2 * half + 0] + bias, 0.f);
                        const float h1 = fmaxf(D[mt][nt][2 * half + 1] + bias, 0.f);
                        acc[nt][0][0] = fmaf(w0, h0, acc[nt][0][0]);
                        acc[nt][0][1] = fmaf(w1, h0, acc[nt][0][1]);
                        acc[nt][1][0] = fmaf(w0, h1, acc[nt][1][0]);
                        acc[nt][1][1] = fmaf(w1, h1, acc[nt][1][1]);
                    }
                }
            #pragma unroll
            for (int o = 4; o <= 16; o <<= 1)
                #pragma unroll
                for (int nt = 0; nt < 2; nt++)
                    #pragma unroll
                    for (int c2 = 0; c2 < 2; c2++) {
                        acc[nt][c2][0] += __shfl_xor_sync(0xffffffffu, acc[nt][c2][0], o);
                        acc[nt][c2][1] += __shfl_xor_sync(0xffffffffu, acc[nt][c2][1], o);
                    }
            if (g == 0) {   // lanes 0..3 hold final sums for their 4 point-columns
                #pragma unroll
                for (int nt = 0; nt < 2; nt++)
                    #pragma unroll
                    for (int c2 = 0; c2 < 2; c2++) {
                        const int pg = pbase + n0 + nt * 8 + 2 * t + c2;
                        if (pg < TOTAL)
                            ((float2*)g_feat)[pg] = make_float2(acc[nt][c2][0] + mf[492],
                                                                acc[nt][c2][1] + mf[493]);
                    }
            }
        }
        // no trailing sync: next tile's layer1 writes H1, whose readers (layer2)
        // finished before sync(2); H2 readers (layer3, this thread) precede the
        // next sync(1) in program order.
    }
}

// ---------------- routing kernel: FOUR queries per block ----------------
__global__ __launch_bounds__(256)
void route_kernel(const int* __restrict__ nbr_idx, const int* __restrict__ labels,
                  float* __restrict__ out)
{
    __shared__ float p_s[4][CC];
    __shared__ float terms[4][DD - 1];

    const int b0 = blockIdx.x * 4;
    const int tid = threadIdx.x;
    const int d = tid >> 5, lane = tid & 31;

    // only warp 7 (d == DD-1) touches p_s: it inits its own region, no block sync needed
    if (d == DD - 1) {
        for (int i = lane; i < 4 * CC; i += 32) ((float*)p_s)[i] = 0.f;
        __syncwarp();
    }

    // issue all 4 index loads, then all 4 gathers (max MLP on the chain)
    int idx4[4];
    #pragma unroll
    for (int u = 0; u < 4; u++) idx4[u] = nbr_idx[(b0 + u) * (DD * KK) + tid];
    float2 q4[4], g4[4];
    #pragma unroll
    for (int u = 0; u < 4; u++) q4[u] = ((const float2*)g_feat)[b0 + u];
    #pragma unroll
    for (int u = 0; u < 4; u++) g4[u] = ((const float2*)g_feat)[BN + idx4[u]];

    float e4[4], s4[4];
    #pragma unroll
    for (int u = 0; u < 4; u++) {
        const float dx = g4[u].x - q4[u].x + 1e-6f;
        const float dy = g4[u].y - q4[u].y + 1e-6f;
        const float dist = sqrtf(fmaf(dx, dx, dy * dy));
        // dist >= 0 -> IEEE bits order-preserving: u32 redux.min == max(-dist)
        const float mind = __uint_as_float(__reduce_min_sync(0xffffffffu, __float_as_uint(dist)));
        e4[u] = __expf(mind - dist);   // argmax lane exactly exp(0) = 1
        s4[u] = e4[u];
    }
    #pragma unroll
    for (int o = 16; o > 0; o >>= 1)
        #pragma unroll
        for (int u = 0; u < 4; u++) s4[u] += __shfl_xor_sync(0xffffffffu, s4[u], o);

    if (d < DD - 1) {
        if (lane == 0) {
            #pragma unroll
            for (int u = 0; u < 4; u++)
                terms[u][d] = __logf(__fdividef(1.0f, s4[u]) + 1e-4f);
        }
    } else {
        #pragma unroll
        for (int u = 0; u < 4; u++) {
            const int c = labels[idx4[u]];
            atomicAdd(&p_s[u][c], __fdividef(e4[u], s4[u]));
        }
    }
    __syncthreads();

    for (int i = tid; i < 4 * CC; i += 256) {
        const int u = i / CC, c = i - u * CC;
        float tsum = terms[u][0] + terms[u][1] + terms[u][2] + terms[u][3]
                   + terms[u][4] + terms[u][5] + terms[u][6];
        out[(long)(b0 + u) * CC + c] = __logf(p_s[u][c] + 1e-4f) + tsum;
    }
}

extern "C" void kernel_launch(void* const* d_in, const int* in_sizes, int n_in,
                              void* d_out, int out_size)
{
    const float* x      = (const float*)d_in[0];
    const float* nd     = (const float*)d_in[1];
    const float* W1     = (const float*)d_in[2];
    const float* b1     = (const float*)d_in[3];
    const float* W2     = (const float*)d_in[4];
    const float* b2     = (const float*)d_in[5];
    const float* W3     = (const float*)d_in[6];
    const float* b3     = (const float*)d_in[7];
    const float* W4     = (const float*)d_in[8];
    const float* b4     = (const float*)d_in[9];
    const int*   labels = (const int*)d_in[10];
    const int*   nbr    = (const int*)d_in[11];
    float* out = (float*)d_out;

    cudaFuncSetAttribute(mlp_kernel, cudaFuncAttributeMaxDynamicSharedMemorySize, SMEM_TOTAL);

    mlp_kernel<<<GRID_MLP, 256, SMEM_TOTAL>>>(x, nd, W1, b1, W2, b2, W3, b3, W4, b4);
    route_kernel<<<BN / 4, 256>>>(nbr, labels, out);
}

// round 16
// speedup vs baseline: 1.6511x; 1.0172x over previous
#include <cuda_runtime.h>
#include <cuda_fp16.h>
#include <math.h>

#define BN 8192
#define NN 100000
#define DD 8
#define KK 32
#define CC 100
#define TOTAL (BN + NN)
#define NTILES ((TOTAL + 127) / 128)   // 846
#define GRID_MLP 296                   // 2 blocks/SM persistent

#define KT   7            // k-tiles of 16 covering K=100 (pad 112)
#define MT2  7            // m-tiles of 16 covering M=100 (pad 112)
#define MT3  2            // m-tiles of 16 covering M=30  (pad 32)

#define NSH  68           // u32 words per point (136 fp16; 68 % 32 == 4 -> conflict-free B frags)

// ---- smem layout (bytes) ----
#define SM_H1    0                       // h1: 128 points * 68 u32 = 34816
#define SM_H2    34816                   // h2: 34816  (separate region)
#define SM_W2F   69632                   // W2 frags: 25088
#define SM_W3F   94720                   // W3 frags: 7168
#define SM_MISC  101888                  // mf floats [494]
#define SMEM_TOTAL 103936                // x2 blocks = 207.9K <= 228K per SM

// Feature scratch: [0..BN) queries, [BN..TOTAL) nodes, (x,y) pairs.
__device__ float g_feat[TOTAL * 2];

__device__ __forceinline__ unsigned h2pk(float lo, float hi) {  // u32 = {lo:lo, hi:hi}
    unsigned r;
    asm("cvt.rn.f16x2.f32 %0, %1, %2;" : "=r"(r) : "f"(hi), "f"(lo));
    return r;
}

__device__ __forceinline__ void mma16(float (&c)[4], const uint4& a, unsigned b0, unsigned b1) {
    asm("mma.sync.aligned.m16n8k16.row.col.f32.f16.f16.f32 "
        "{%0,%1,%2,%3}, {%4,%5,%6,%7}, {%8,%9}, {%0,%1,%2,%3};"
        : "+f"(c[0]), "+f"(c[1]), "+f"(c[2]), "+f"(c[3])
        : "r"(a.x), "r"(a.y), "r"(a.z), "r"(a.w), "r"(b0), "r"(b1));
}

// ---------------- persistent MLP kernel: 256 threads, 128 points per tile ----------------
// Tile loop is BARRIER-FREE across warps: each warp owns 16 points end-to-end
// (layer1 -> layer2 mma -> epilogue -> layer3 mma -> layer4), only __syncwarp.
__global__ __launch_bounds__(256, 2)
void mlp_kernel(const float* __restrict__ x, const float* __restrict__ nd,
                const float* __restrict__ W1, const float* __restrict__ b1,
                const float* __restrict__ W2, const float* __restrict__ b2,
                const float* __restrict__ W3, const float* __restrict__ b3,
                const float* __restrict__ W4, const float* __restrict__ b4)
{
    extern __shared__ char smraw[];
    unsigned* H1W = (unsigned*)(smraw + SM_H1);     // [point][kword] fp16x2
    unsigned* H2W = (unsigned*)(smraw + SM_H2);
    __half*   H2h = (__half*)(smraw + SM_H2);
    const uint4* W2F = (const uint4*)(smraw + SM_W2F);
    const uint4* W3F = (const uint4*)(smraw + SM_W3F);
    float* mf = (float*)(smraw + SM_MISC);

    const int tid = threadIdx.x;
    const int lane = tid & 31, warp = tid >> 5;
    const int g = lane >> 2, t = lane & 3;
    const int n0 = warp * 16;              // each warp owns 16 points (2 n-tiles of 8)

    // ---- phase 0: zero smem, inline coalesced pack of W2/W3, params (block-synced, once) ----
    {
        uint4* z = (uint4*)smraw;
        for (int i = tid; i < SM_MISC / 16; i += 256) z[i] = make_uint4(0, 0, 0, 0);
        __syncthreads();

        // frag layout: u32 id = ((kt*MT+mt)*32 + ln)*4 + r
        //   row = mt*16 + (ln>>2) + (r&1)*8 ; col = kt*16 + 2*(ln&3) + (r>>1)*8 (+b)
        __half* W2Fh = (__half*)(smraw + SM_W2F);
        for (int i = tid; i < 2500; i += 256) {
            const float4 w = ((const float4*)W2)[i];
            const float we[4] = {w.x, w.y, w.z, w.w};
            const int base = i * 4;
            #pragma unroll
            for (int e = 0; e < 4; e++) {
                const int idx = base + e;
                const int row = idx / 100, col = idx - row * 100;
                const int mt = row >> 4, rr = row & 15;
                const int kt = col >> 4, cc = col & 15;
                const int ln = (rr & 7) * 4 + ((cc >> 1) & 3);
                const int r = (rr >> 3) + ((cc >> 3) << 1);
                const int fid = ((kt * MT2 + mt) * 32 + ln) * 4 + r;
                W2Fh[fid * 2 + (cc & 1)] = __float2half_rn(we[e]);
            }
        }
        __half* W3Fh = (__half*)(smraw + SM_W3F);
        for (int i = tid; i < 750; i += 256) {
            const float4 w = ((const float4*)W3)[i];
            const float we[4] = {w.x, w.y, w.z, w.w};
            const int base = i * 4;
            #pragma unroll
            for (int e = 0; e < 4; e++) {
                const int idx = base + e;
                const int row = idx / 100, col = idx - row * 100;
                const int mt = row >> 4, rr = row & 15;
                const int kt = col >> 4, cc = col & 15;
                const int ln = (rr & 7) * 4 + ((cc >> 1) & 3);
                const int r = (rr >> 3) + ((cc >> 3) << 1);
                const int fid = ((kt * MT3 + mt) * 32 + ln) * 4 + r;
                W3Fh[fid * 2 + (cc & 1)] = __float2half_rn(we[e]);
            }
        }
        for (int i = tid; i < 200; i += 256) mf[i] = W1[i];
        if (tid < 100) { mf[200 + tid] = b1[tid]; mf[300 + tid] = b2[tid]; }
        if (tid < 32)  mf[400 + tid] = (tid < 30) ? b3[tid] : 0.f;
        if (tid < 60)  mf[432 + tid] = W4[tid];
        if (tid < 2)   mf[492 + tid] = b4[tid];
    }
    __syncthreads();

    for (int tile = blockIdx.x; tile < NTILES; tile += GRID_MLP) {
        const int pbase = tile * 128;

        // ---- layer 1: warp computes its OWN 16 points (lane = point x j-half) ----
        {
            const int p_loc = lane & 15, half = lane >> 4;
            const int p = n0 + p_loc;
            const int pg = pbase + p;
            float px = 0.f, py = 0.f;
            if (pg < TOTAL) {
                const float2 v = (pg < BN) ? ((const float2*)x)[pg]
                                           : ((const float2*)nd)[pg - BN];
                px = v.x; py = v.y;
            }
            const int j0 = half * 50;
            unsigned* dst = H1W + p * NSH + (j0 >> 1);
            #pragma unroll 5
            for (int j2 = 0; j2 < 25; j2++) {
                const int j = j0 + 2 * j2;
                const float v0 = fmaxf(fmaf(mf[2 * j], px,
                                       fmaf(mf[2 * j + 1], py, mf[200 + j])), 0.f);
                const float v1 = fmaxf(fmaf(mf[2 * j + 2], px,
                                       fmaf(mf[2 * j + 3], py, mf[201 + j])), 0.f);
                dst[j2] = h2pk(v0, v1);
            }
        }
        __syncwarp();   // H1 rows n0..n0+15 ready for this warp's B-frag reads

        // ---- layer 2: 100 -> 100 via fp16 mma reading own H1 rows ----
        float C[MT2][2][4];
        #pragma unroll
        for (int mt = 0; mt < MT2; mt++)
            #pragma unroll
            for (int nt = 0; nt < 2; nt++)
                #pragma unroll
                for (int r = 0; r < 4; r++) C[mt][nt][r] = 0.f;

        const unsigned* a0p = H1W + (n0 + g) * NSH + t;
        const unsigned* a1p = H1W + (n0 + 8 + g) * NSH + t;
        for (int kt = 0; kt < KT; kt++) {
            const int kw = kt * 8;
            unsigned bf[2][2];
            bf[0][0] = a0p[kw];     bf[0][1] = a0p[kw + 4];
            bf[1][0] = a1p[kw];     bf[1][1] = a1p[kw + 4];
            #pragma unroll
            for (int mt = 0; mt < MT2; mt++) {
                const uint4 a = W2F[(kt * MT2 + mt) * 32 + lane];
                mma16(C[mt][0], a, bf[0][0], bf[0][1]);
                mma16(C[mt][1], a, bf[1][0], bf[1][1]);
            }
        }

        // epilogue: h2 = relu(C + b2) -> own H2 rows (warp-internal)
        #pragma unroll
        for (int mt = 0; mt < MT2; mt++)
            #pragma unroll
            for (int half = 0; half < 2; half++) {
                const int row = mt * 16 + g + half * 8;
                const float bias = (row < 100) ? mf[300 + row] : 0.f;
                #pragma unroll
                for (int nt = 0; nt < 2; nt++) {
                    float v0 = C[mt][nt][2 * half + 0] + bias;
                    float v1 = C[mt][nt][2 * half + 1] + bias;
                    if (row >= 100) { v0 = 0.f; v1 = 0.f; }
                    else { v0 = fmaxf(v0, 0.f); v1 = fmaxf(v1, 0.f); }
                    const int p0 = n0 + nt * 8 + 2 * t;
                    H2h[p0 * (2 * NSH) + row] = __float2half_rn(v0);
                    H2h[(p0 + 1) * (2 * NSH) + row] = __float2half_rn(v1);
                }
            }
        __syncwarp();   // H2 rows n0..n0+15 ready

        // ---- layer 3: 100 -> 30 via fp16 mma reading own H2 rows ----
        float D[MT3][2][4];
        #pragma unroll
        for (int mt = 0; mt < MT3; mt++)
            #pragma unroll
            for (int nt = 0; nt < 2; nt++)
                #pragma unroll
                for (int r = 0; r < 4; r++) D[mt][nt][r] = 0.f;

        const unsigned* c0p = H2W + (n0 + g) * NSH + t;
        const unsigned* c1p = H2W + (n0 + 8 + g) * NSH + t;
        for (int kt = 0; kt < KT; kt++) {
            const int kw = kt * 8;
            unsigned bf[2][2];
            bf[0][0] = c0p[kw];     bf[0][1] = c0p[kw + 4];
            bf[1][0] = c1p[kw];     bf[1][1] = c1p[kw + 4];
            #pragma unroll
            for (int mt = 0; mt < MT3; mt++) {
                const uint4 a = W3F[(kt * MT3 + mt) * 32 + lane];
                mma16(D[mt][0], a, bf[0][0], bf[0][1]);
                mma16(D[mt][1], a, bf[1][0], bf[1][1]);
            }
        }

        // ---- layer 4: 30 -> 2 directly from D fragments, warp shuffle reduce ----
        {
            float acc[2][2][2];   // [nt][col01][out01]
            #pragma unroll
            for (int nt = 0; nt < 2; nt++)
                #pragma unroll
                for (int c2 = 0; c2 < 2; c2++) { acc[nt][c2][0] = 0.f; acc[nt][c2][1] = 0.f; }
            #pragma unroll
            for (int mt = 0; mt < MT3; mt++)
                #pragma unroll
                for (int half = 0; half < 2; half++) {
                    const int row = mt * 16 + g + half * 8;
                    const float w0 = (row < 30) ? mf[432 + row] : 0.f;   // W4[0][row]
                    const float w1 = (row < 30) ? mf[462 + row] : 0.f;   // W4[1][row]
                    const float bias = (row < 30) ? mf[400 + row] : 0.f;
                    #pragma unroll
                    for (int nt = 0; nt < 2; nt++) {
                        const float h0 = fmaxf(D[mt][nt][2 * half + 0] + bias, 0.f);
                        const float h1 = fmaxf(D[mt][nt][2 * half + 1] + bias, 0.f);
                        acc[nt][0][0] = fmaf(w0, h0, acc[nt][0][0]);
                        acc[nt][0][1] = fmaf(w1, h0, acc[nt][0][1]);
                        acc[nt][1][0] = fmaf(w0, h1, acc[nt][1][0]);
                        acc[nt][1][1] = fmaf(w1, h1, acc[nt][1][1]);
                    }
                }
            #pragma unroll
            for (int o = 4; o <= 16; o <<= 1)
                #pragma unroll
                for (int nt = 0; nt < 2; nt++)
                    #pragma unroll
                    for (int c2 = 0; c2 < 2; c2++) {
                        acc[nt][c2][0] += __shfl_xor_sync(0xffffffffu, acc[nt][c2][0], o);
                        acc[nt][c2][1] += __shfl_xor_sync(0xffffffffu, acc[nt][c2][1], o);
                    }
            if (g == 0) {   // lanes 0..3 hold final sums for their 4 point-columns
                #pragma unroll
                for (int nt = 0; nt < 2; nt++)
                    #pragma unroll
                    for (int c2 = 0; c2 < 2; c2++) {
                        const int pg = pbase + n0 + nt * 8 + 2 * t + c2;
                        if (pg < TOTAL)
                            ((float2*)g_feat)[pg] = make_float2(acc[nt][c2][0] + mf[492],
                                                                acc[nt][c2][1] + mf[493]);
                    }
            }
        }
        __syncwarp();   // all lanes' H1/H2 reads done before next tile's layer-1 writes
    }
}

// ---------------- routing kernel: FOUR queries per block ----------------
__global__ __launch_bounds__(256)
void route_kernel(const int* __restrict__ nbr_idx, const int* __restrict__ labels,
                  float* __restrict__ out)
{
    __shared__ float p_s[4][CC];
    __shared__ float terms[4][DD - 1];

    const int b0 = blockIdx.x * 4;
    const int tid = threadIdx.x;
    const int d = tid >> 5, lane = tid & 31;

    // only warp 7 (d == DD-1) touches p_s: it inits its own region, no block sync needed
    if (d == DD - 1) {
        for (int i = lane; i < 4 * CC; i += 32) ((float*)p_s)[i] = 0.f;
        __syncwarp();
    }

    // issue all 4 index loads, then all 4 gathers (max MLP on the chain)
    int idx4[4];
    #pragma unroll
    for (int u = 0; u < 4; u++) idx4[u] = nbr_idx[(b0 + u) * (DD * KK) + tid];
    float2 q4[4], g4[4];
    #pragma unroll
    for (int u = 0; u < 4; u++) q4[u] = ((const float2*)g_feat)[b0 + u];
    #pragma unroll
    for (int u = 0; u < 4; u++) g4[u] = ((const float2*)g_feat)[BN + idx4[u]];

    float e4[4], s4[4];
    #pragma unroll
    for (int u = 0; u < 4; u++) {
        const float dx = g4[u].x - q4[u].x + 1e-6f;
        const float dy = g4[u].y - q4[u].y + 1e-6f;
        const float dist = sqrtf(fmaf(dx, dx, dy * dy));
        // dist >= 0 -> IEEE bits order-preserving: u32 redux.min == max(-dist)
        const float mind = __uint_as_float(__reduce_min_sync(0xffffffffu, __float_as_uint(dist)));
        e4[u] = __expf(mind - dist);   // argmax lane exactly exp(0) = 1
        s4[u] = e4[u];
    }
    #pragma unroll
    for (int o = 16; o > 0; o >>= 1)
        #pragma unroll
        for (int u = 0; u < 4; u++) s4[u] += __shfl_xor_sync(0xffffffffu, s4[u], o);

    if (d < DD - 1) {
        if (lane == 0) {
            #pragma unroll
            for (int u = 0; u < 4; u++)
                terms[u][d] = __logf(__fdividef(1.0f, s4[u]) + 1e-4f);
        }
    } else {
        #pragma unroll
        for (int u = 0; u < 4; u++) {
            const int c = labels[idx4[u]];
            atomicAdd(&p_s[u][c], __fdividef(e4[u], s4[u]));
        }
    }
    __syncthreads();

    for (int i = tid; i < 4 * CC; i += 256) {
        const int u = i / CC, c = i - u * CC;
        float tsum = terms[u][0] + terms[u][1] + terms[u][2] + terms[u][3]
                   + terms[u][4] + terms[u][5] + terms[u][6];
        out[(long)(b0 + u) * CC + c] = __logf(p_s[u][c] + 1e-4f) + tsum;
    }
}

extern "C" void kernel_launch(void* const* d_in, const int* in_sizes, int n_in,
                              void* d_out, int out_size)
{
    const float* x      = (const float*)d_in[0];
    const float* nd     = (const float*)d_in[1];
    const float* W1     = (const float*)d_in[2];
    const float* b1     = (const float*)d_in[3];
    const float* W2     = (const float*)d_in[4];
    const float* b2     = (const float*)d_in[5];
    const float* W3     = (const float*)d_in[6];
    const float* b3     = (const float*)d_in[7];
    const float* W4     = (const float*)d_in[8];
    const float* b4     = (const float*)d_in[9];
    const int*   labels = (const int*)d_in[10];
    const int*   nbr    = (const int*)d_in[11];
    float* out = (float*)d_out;

    cudaFuncSetAttribute(mlp_kernel, cudaFuncAttributeMaxDynamicSharedMemorySize, SMEM_TOTAL);

    mlp_kernel<<<GRID_MLP, 256, SMEM_TOTAL>>>(x, nd, W1, b1, W2, b2, W3, b3, W4, b4);
    route_kernel<<<BN / 4, 256>>>(nbr, labels, out);
}